// round 8
// baseline (speedup 1.0000x reference)
#include <cuda_runtime.h>
#include <cstdint>

// Problem constants
#define BH_   64      // B*H = 4*16
#define M_    64      // number of blocks m = N/b
#define BB_   128     // block size b
#define D_    64      // head dim
#define N_    8192
#define SCALE_ 0.125f // 1/sqrt(64)
#define EPS_   1e-6f
#define NSTEPS_ 3

// Scratch (device globals; no allocation allowed)
__device__ float g_KBAR[(size_t)BH_*BB_*M_*D_];  // [bh][l][k][d]
__device__ float g_QBAR[(size_t)BH_*M_*BB_*D_];  // [bh][k][l][d]
__device__ float g_LBUF[(size_t)BH_*BB_*M_*M_];  // [bh][l][i][k] (tf32 patterns)
__device__ float g_VBAR[(size_t)BH_*BB_*M_*D_];  // [bh][l][k][d]

// ---------------------------------------------------------------------------
// tf32 mma helpers  (m16n8k8, A row-major, B col-major, fp32 accum)
// A frag: a0:(g,t) a1:(g+8,t) a2:(g,t+4) a3:(g+8,t+4)   [g=lane>>2, t=lane&3]
// B frag: b0:(t,g) b1:(t+4,g)
// C frag: c0:(g,2t) c1:(g,2t+1) c2:(g+8,2t) c3:(g+8,2t+1)
// Operand tiles are pre-converted to tf32 bit patterns at smem-store time;
// fragment loads are plain LDS reinterpreted as uint32.
// ---------------------------------------------------------------------------
__device__ __forceinline__ uint32_t f2tf(float x){
    uint32_t r; asm("cvt.rna.tf32.f32 %0, %1;" : "=r"(r) : "f"(x)); return r;
}
__device__ __forceinline__ float f2tf_f(float x){
    return __uint_as_float(f2tf(x));
}
__device__ __forceinline__ void mma8(float* c,
    uint32_t a0, uint32_t a1, uint32_t a2, uint32_t a3,
    uint32_t b0, uint32_t b1)
{
    asm volatile("mma.sync.aligned.m16n8k8.row.col.f32.tf32.tf32.f32 "
        "{%0,%1,%2,%3},{%4,%5,%6,%7},{%8,%9},{%0,%1,%2,%3};"
        : "+f"(c[0]), "+f"(c[1]), "+f"(c[2]), "+f"(c[3])
        : "r"(a0), "r"(a1), "r"(a2), "r"(a3), "r"(b0), "r"(b1));
}
#define U(x) __float_as_uint(x)

// ---------------------------------------------------------------------------
// Kernel 1: Kbar init = broadcast mean over l' of K block k
// ---------------------------------------------------------------------------
__global__ __launch_bounds__(256)
void init_kbar_kernel(const float* __restrict__ K)
{
    int k  = blockIdx.x;
    int bh = blockIdx.y;
    int tid = threadIdx.x;
    int d = tid & 63;
    int g = tid >> 6;          // 0..3

    __shared__ float red[4][64];

    const float* Kg = K + ((size_t)bh * N_ + (size_t)k * BB_) * D_;
    float s = 0.f;
    for (int lp = g; lp < BB_; lp += 4)
        s += Kg[(size_t)lp * D_ + d];
    red[g][d] = s;
    __syncthreads();

    __shared__ float meanv[64];
    if (tid < 64) {
        meanv[tid] = (red[0][tid] + red[1][tid] + red[2][tid] + red[3][tid]) * (1.0f / BB_);
    }
    __syncthreads();

    float mv = meanv[d];
    float* dst = g_KBAR + ((size_t)bh * BB_ * M_ + (size_t)k) * D_; // + l*M_*D_
    for (int l = g; l < BB_; l += 4)
        dst[(size_t)l * M_ * D_ + d] = mv;
}

// ---------------------------------------------------------------------------
// Kernel 2 (tensor): per (bh, l):
//   S = scale * Q_l (64x64) @ Kbar_l^T ; L = softmax_k(S)
//   Qbar[k][d] = (L^T @ Q_l)[k][d] / (w[k]+eps)
// grid (128, 64), 256 threads (8 warps: 4 row-groups x 2 col-groups)
// ---------------------------------------------------------------------------
#define KL_PQ 72
#define KL_PK 68
#define KL_PL 72
#define KL_SMEM_FLOATS (64*KL_PQ + 64*KL_PK + 64*KL_PL + 64)
#define KL_SMEM_BYTES  (KL_SMEM_FLOATS * 4)

__global__ __launch_bounds__(256, 4)
void kl_kernel(const float* __restrict__ Q, int writeL)
{
    extern __shared__ float sm[];
    float* Qs  = sm;                         // [64][72]  tf32 patterns
    float* Ks  = Qs + 64 * KL_PQ;            // [64][68]  Kbar_l tf32 patterns
    float* Ls  = Ks + 64 * KL_PK;            // [64][72]  fp32 scores -> tf32 probs
    float* wsh = Ls + 64 * KL_PL;            // [64]

    int l  = blockIdx.x;
    int bh = blockIdx.y;
    int tid = threadIdx.x;
    int lane = tid & 31, wid = tid >> 5;
    int g = lane >> 2, t = lane & 3;

    // Load Q_l rows (strided in gmem) and Kbar_l (contiguous); convert once.
    const float* Qg = Q + (size_t)bh * N_ * D_ + (size_t)l * D_;
    for (int idx = tid; idx < 64 * 16; idx += 256) {
        int i = idx >> 4, d4 = idx & 15;
        float4 v = *(const float4*)(Qg + (size_t)i * BB_ * D_ + d4 * 4);
        float* p = Qs + i * KL_PQ + d4 * 4;
        p[0] = f2tf_f(v.x); p[1] = f2tf_f(v.y); p[2] = f2tf_f(v.z); p[3] = f2tf_f(v.w);
    }
    const float* Kg = g_KBAR + ((size_t)bh * BB_ + l) * M_ * D_;
    for (int idx = tid; idx < 64 * 16; idx += 256) {
        int kk = idx >> 4, d4 = idx & 15;
        float4 v = *(const float4*)(Kg + idx * 4);
        float* p = Ks + kk * KL_PK + d4 * 4;
        p[0] = f2tf_f(v.x); p[1] = f2tf_f(v.y); p[2] = f2tf_f(v.z); p[3] = f2tf_f(v.w);
    }
    __syncthreads();

    int wr = wid >> 1, wc = wid & 1;
    int m0 = wr * 16;

    // GEMM1: S[i][k] = sum_d Q[i][d] * Kbar[k][d]
    float acc[4][4];
#pragma unroll
    for (int nt = 0; nt < 4; nt++)
#pragma unroll
        for (int e = 0; e < 4; e++) acc[nt][e] = 0.f;

#pragma unroll
    for (int s = 0; s < 8; s++) {
        int k0 = s * 8;
        uint32_t a0 = U(Qs[(m0 + g    ) * KL_PQ + k0 + t    ]);
        uint32_t a1 = U(Qs[(m0 + g + 8) * KL_PQ + k0 + t    ]);
        uint32_t a2 = U(Qs[(m0 + g    ) * KL_PQ + k0 + t + 4]);
        uint32_t a3 = U(Qs[(m0 + g + 8) * KL_PQ + k0 + t + 4]);
#pragma unroll
        for (int nt = 0; nt < 4; nt++) {
            int n0 = wc * 32 + nt * 8;
            uint32_t b0 = U(Ks[(n0 + g) * KL_PK + k0 + t    ]);
            uint32_t b1 = U(Ks[(n0 + g) * KL_PK + k0 + t + 4]);
            mma8(acc[nt], a0, a1, a2, a3, b0, b1);
        }
    }

    // scaled fp32 scores -> Ls
#pragma unroll
    for (int nt = 0; nt < 4; nt++) {
        int n0 = wc * 32 + nt * 8;
        Ls[(m0 + g    ) * KL_PL + n0 + 2 * t    ] = acc[nt][0] * SCALE_;
        Ls[(m0 + g    ) * KL_PL + n0 + 2 * t + 1] = acc[nt][1] * SCALE_;
        Ls[(m0 + g + 8) * KL_PL + n0 + 2 * t    ] = acc[nt][2] * SCALE_;
        Ls[(m0 + g + 8) * KL_PL + n0 + 2 * t + 1] = acc[nt][3] * SCALE_;
    }
    __syncthreads();

    // softmax over k (fp32), write back tf32-rounded probabilities
    {
        int row = tid >> 2, q = tid & 3;
        float* rp = Ls + row * KL_PL + q * 16;
        float vv[16];
#pragma unroll
        for (int j = 0; j < 4; j++) *(float4*)(vv + 4 * j) = *(float4*)(rp + 4 * j);
        float mx = -1e30f;
#pragma unroll
        for (int j = 0; j < 16; j++) mx = fmaxf(mx, vv[j]);
        mx = fmaxf(mx, __shfl_xor_sync(0xffffffffu, mx, 1));
        mx = fmaxf(mx, __shfl_xor_sync(0xffffffffu, mx, 2));
        float ssum = 0.f;
#pragma unroll
        for (int j = 0; j < 16; j++) { vv[j] = __expf(vv[j] - mx); ssum += vv[j]; }
        ssum += __shfl_xor_sync(0xffffffffu, ssum, 1);
        ssum += __shfl_xor_sync(0xffffffffu, ssum, 2);
        float inv = 1.0f / ssum;
#pragma unroll
        for (int j = 0; j < 16; j++) vv[j] = f2tf_f(vv[j] * inv);
#pragma unroll
        for (int j = 0; j < 4; j++) *(float4*)(rp + 4 * j) = *(float4*)(vv + 4 * j);
    }
    __syncthreads();

    // w[k] = sum_i L[i][k] (tf32 patterns are valid fp32); stash 1/(w+eps)
    if (tid < 64) {
        float s = 0.f;
#pragma unroll 8
        for (int i = 0; i < 64; i++) s += Ls[i * KL_PL + tid];
        wsh[tid] = 1.0f / (s + EPS_);
    }
    if (writeL) {
        float* Lg = g_LBUF + ((size_t)bh * BB_ + l) * M_ * M_;
        for (int idx = tid; idx < 64 * 16; idx += 256) {
            int i = idx >> 4, k4 = idx & 15;
            float* p = Ls + i * KL_PL + k4 * 4;
            *(float4*)(Lg + idx * 4) = make_float4(p[0], p[1], p[2], p[3]);
        }
    }
    __syncthreads();

    // GEMM2: Qbar[k][d] = sum_i L[i][k] * Q[i][d]   (A = L^T read transposed)
    float acc2[4][4];
#pragma unroll
    for (int nt = 0; nt < 4; nt++)
#pragma unroll
        for (int e = 0; e < 4; e++) acc2[nt][e] = 0.f;

#pragma unroll
    for (int s = 0; s < 8; s++) {
        int i0 = s * 8;
        uint32_t a0 = U(Ls[(i0 + t    ) * KL_PL + m0 + g    ]);
        uint32_t a1 = U(Ls[(i0 + t    ) * KL_PL + m0 + g + 8]);
        uint32_t a2 = U(Ls[(i0 + t + 4) * KL_PL + m0 + g    ]);
        uint32_t a3 = U(Ls[(i0 + t + 4) * KL_PL + m0 + g + 8]);
#pragma unroll
        for (int nt = 0; nt < 4; nt++) {
            int n0 = wc * 32 + nt * 8;
            uint32_t b0 = U(Qs[(i0 + t    ) * KL_PQ + n0 + g]);
            uint32_t b1 = U(Qs[(i0 + t + 4) * KL_PQ + n0 + g]);
            mma8(acc2[nt], a0, a1, a2, a3, b0, b1);
        }
    }

    float* Qbg = g_QBAR + (size_t)bh * M_ * BB_ * D_ + (size_t)l * D_;
    float w0 = wsh[m0 + g], w1 = wsh[m0 + g + 8];
#pragma unroll
    for (int nt = 0; nt < 4; nt++) {
        int n0 = wc * 32 + nt * 8;
        *(float2*)(Qbg + (size_t)(m0 + g    ) * BB_ * D_ + n0 + 2 * t) =
            make_float2(acc2[nt][0] * w0, acc2[nt][1] * w0);
        *(float2*)(Qbg + (size_t)(m0 + g + 8) * BB_ * D_ + n0 + 2 * t) =
            make_float2(acc2[nt][2] * w1, acc2[nt][3] * w1);
    }
}

// ---------------------------------------------------------------------------
// Kernel 3 (tensor): per (bh, k):
//   S = scale * Qbar_k (128x64) @ K_k^T ; R = softmax_{l'}(S)
//   Kbar = R @ K_k   (or Vbar = R @ V_k on last iter)
// grid (64, 64), 256 threads.  Scores held in regs; Rs aliases Qbs region.
// ---------------------------------------------------------------------------
#define KR_PQ 68
#define KR_PK 68
#define KR_PR 132
#define KR_SMEM_FLOATS (BB_*KR_PR + BB_*KR_PK)
#define KR_SMEM_BYTES  (KR_SMEM_FLOATS * 4)

__global__ __launch_bounds__(256, 2)
void kr_kernel(const float* __restrict__ K, const float* __restrict__ V, int last)
{
    extern __shared__ float sm[];
    float* Rs  = sm;                  // [128][132]; prefix doubles as Qbs[128][68]
    float* Qbs = sm;
    float* Ks  = sm + BB_ * KR_PR;    // [128][68]  K_k tf32, V_k tf32 on last

    int k  = blockIdx.x;
    int bh = blockIdx.y;
    int tid = threadIdx.x;
    int lane = tid & 31, wid = tid >> 5;
    int g = lane >> 2, t = lane & 3;

    const float* Qbg = g_QBAR + ((size_t)bh * M_ + k) * BB_ * D_;
    for (int idx = tid; idx < BB_ * 16; idx += 256) {
        int ll = idx >> 4, d4 = idx & 15;
        float4 v = *(const float4*)(Qbg + idx * 4);
        float* p = Qbs + ll * KR_PQ + d4 * 4;
        p[0] = f2tf_f(v.x); p[1] = f2tf_f(v.y); p[2] = f2tf_f(v.z); p[3] = f2tf_f(v.w);
    }
    const float* Kg = K + ((size_t)bh * N_ + (size_t)k * BB_) * D_;
    for (int idx = tid; idx < BB_ * 16; idx += 256) {
        int ll = idx >> 4, d4 = idx & 15;
        float4 v = *(const float4*)(Kg + idx * 4);
        float* p = Ks + ll * KR_PK + d4 * 4;
        p[0] = f2tf_f(v.x); p[1] = f2tf_f(v.y); p[2] = f2tf_f(v.z); p[3] = f2tf_f(v.w);
    }
    __syncthreads();

    int wr = wid >> 1, wc = wid & 1;

    // GEMM1: S[l][l'] (128x128), accum fully in registers (64 f32/lane)
    float acc1[2][8][4];
#pragma unroll
    for (int mt = 0; mt < 2; mt++)
#pragma unroll
        for (int nt = 0; nt < 8; nt++)
#pragma unroll
            for (int e = 0; e < 4; e++) acc1[mt][nt][e] = 0.f;

#pragma unroll
    for (int s = 0; s < 8; s++) {
        int d0 = s * 8;
        uint32_t a[2][4];
#pragma unroll
        for (int mt = 0; mt < 2; mt++) {
            int m0 = wr * 32 + mt * 16;
            a[mt][0] = U(Qbs[(m0 + g    ) * KR_PQ + d0 + t    ]);
            a[mt][1] = U(Qbs[(m0 + g + 8) * KR_PQ + d0 + t    ]);
            a[mt][2] = U(Qbs[(m0 + g    ) * KR_PQ + d0 + t + 4]);
            a[mt][3] = U(Qbs[(m0 + g + 8) * KR_PQ + d0 + t + 4]);
        }
#pragma unroll
        for (int nt = 0; nt < 8; nt++) {
            int n0 = wc * 64 + nt * 8;
            uint32_t b0 = U(Ks[(n0 + g) * KR_PK + d0 + t    ]);
            uint32_t b1 = U(Ks[(n0 + g) * KR_PK + d0 + t + 4]);
            mma8(acc1[0][nt], a[0][0], a[0][1], a[0][2], a[0][3], b0, b1);
            mma8(acc1[1][nt], a[1][0], a[1][1], a[1][2], a[1][3], b0, b1);
        }
    }
    __syncthreads();   // all Qbs reads done before scores overwrite the region

    // scaled fp32 scores -> Rs
#pragma unroll
    for (int mt = 0; mt < 2; mt++) {
        int m0 = wr * 32 + mt * 16;
#pragma unroll
        for (int nt = 0; nt < 8; nt++) {
            int n0 = wc * 64 + nt * 8;
            Rs[(m0 + g    ) * KR_PR + n0 + 2 * t    ] = acc1[mt][nt][0] * SCALE_;
            Rs[(m0 + g    ) * KR_PR + n0 + 2 * t + 1] = acc1[mt][nt][1] * SCALE_;
            Rs[(m0 + g + 8) * KR_PR + n0 + 2 * t    ] = acc1[mt][nt][2] * SCALE_;
            Rs[(m0 + g + 8) * KR_PR + n0 + 2 * t + 1] = acc1[mt][nt][3] * SCALE_;
        }
    }
    // On last iter: V replaces K as the second-GEMM operand (K reads are done)
    if (last) {
        const float* Vg = V + ((size_t)bh * N_ + (size_t)k * BB_) * D_;
        for (int idx = tid; idx < BB_ * 16; idx += 256) {
            int ll = idx >> 4, d4 = idx & 15;
            float4 v = *(const float4*)(Vg + idx * 4);
            float* p = Ks + ll * KR_PK + d4 * 4;
            p[0] = f2tf_f(v.x); p[1] = f2tf_f(v.y); p[2] = f2tf_f(v.z); p[3] = f2tf_f(v.w);
        }
    }
    __syncthreads();

    // softmax over l' (fp32), write back tf32-rounded probabilities
    {
        int row = tid >> 1, h = tid & 1;
        float* rp = Rs + row * KR_PR + h * 64;
        float vv[64];
#pragma unroll
        for (int j = 0; j < 16; j++) *(float4*)(vv + 4 * j) = *(float4*)(rp + 4 * j);
        float mx = -1e30f;
#pragma unroll
        for (int j = 0; j < 64; j++) mx = fmaxf(mx, vv[j]);
        mx = fmaxf(mx, __shfl_xor_sync(0xffffffffu, mx, 1));
        float ssum = 0.f;
#pragma unroll
        for (int j = 0; j < 64; j++) { vv[j] = __expf(vv[j] - mx); ssum += vv[j]; }
        ssum += __shfl_xor_sync(0xffffffffu, ssum, 1);
        float inv = 1.0f / ssum;
#pragma unroll
        for (int j = 0; j < 64; j++) vv[j] = f2tf_f(vv[j] * inv);
#pragma unroll
        for (int j = 0; j < 16; j++) *(float4*)(rp + 4 * j) = *(float4*)(vv + 4 * j);
    }
    __syncthreads();

    // GEMM2: out[l][d] = sum_{l'} R[l][l'] * Op[l'][d]
    float acc2[2][4][4];
#pragma unroll
    for (int mt = 0; mt < 2; mt++)
#pragma unroll
        for (int nt = 0; nt < 4; nt++)
#pragma unroll
            for (int e = 0; e < 4; e++) acc2[mt][nt][e] = 0.f;

#pragma unroll
    for (int s = 0; s < 16; s++) {
        int kk0 = s * 8;
        uint32_t a[2][4];
#pragma unroll
        for (int mt = 0; mt < 2; mt++) {
            int m0 = wr * 32 + mt * 16;
            a[mt][0] = U(Rs[(m0 + g    ) * KR_PR + kk0 + t    ]);
            a[mt][1] = U(Rs[(m0 + g + 8) * KR_PR + kk0 + t    ]);
            a[mt][2] = U(Rs[(m0 + g    ) * KR_PR + kk0 + t + 4]);
            a[mt][3] = U(Rs[(m0 + g + 8) * KR_PR + kk0 + t + 4]);
        }
#pragma unroll
        for (int nt = 0; nt < 4; nt++) {
            int n0 = wc * 32 + nt * 8;
            uint32_t b0 = U(Ks[(kk0 + t    ) * KR_PK + n0 + g]);
            uint32_t b1 = U(Ks[(kk0 + t + 4) * KR_PK + n0 + g]);
            mma8(acc2[0][nt], a[0][0], a[0][1], a[0][2], a[0][3], b0, b1);
            mma8(acc2[1][nt], a[1][0], a[1][1], a[1][2], a[1][3], b0, b1);
        }
    }

    float* dst = (last ? g_VBAR : g_KBAR) + ((size_t)bh * BB_ * M_ + (size_t)k) * D_;
#pragma unroll
    for (int mt = 0; mt < 2; mt++) {
        int m0 = wr * 32 + mt * 16;
#pragma unroll
        for (int nt = 0; nt < 4; nt++) {
            int n0 = wc * 32 + nt * 8;
            *(float2*)(dst + (size_t)(m0 + g    ) * M_ * D_ + n0 + 2 * t) =
                make_float2(acc2[mt][nt][0], acc2[mt][nt][1]);
            *(float2*)(dst + (size_t)(m0 + g + 8) * M_ * D_ + n0 + 2 * t) =
                make_float2(acc2[mt][nt][2], acc2[mt][nt][3]);
        }
    }
}

// ---------------------------------------------------------------------------
// Kernel 4 (tensor): per (bh, l): out[i][d] = sum_k L[i][k] * Vbar[k][d]
// grid (128, 64), 256 threads.  L already tf32 in gmem.
// ---------------------------------------------------------------------------
#define OUT_PL 68
#define OUT_PV 72
__global__ __launch_bounds__(256, 4)
void out_kernel(float* __restrict__ O)
{
    __shared__ float Ls[64 * OUT_PL];
    __shared__ float Vbs[64 * OUT_PV];

    int l  = blockIdx.x;
    int bh = blockIdx.y;
    int tid = threadIdx.x;
    int lane = tid & 31, wid = tid >> 5;
    int g = lane >> 2, t = lane & 3;

    const float* Lg = g_LBUF + ((size_t)bh * BB_ + l) * M_ * M_;
    for (int idx = tid; idx < 64 * 16; idx += 256) {
        int i = idx >> 4, k4 = idx & 15;
        float4 v = *(const float4*)(Lg + idx * 4);   // already tf32 patterns
        float* p = Ls + i * OUT_PL + k4 * 4;
        p[0] = v.x; p[1] = v.y; p[2] = v.z; p[3] = v.w;
    }
    const float* Vg = g_VBAR + ((size_t)bh * BB_ + l) * M_ * D_;
    for (int idx = tid; idx < 64 * 16; idx += 256) {
        int kk = idx >> 4, d4 = idx & 15;
        float4 v = *(const float4*)(Vg + idx * 4);
        float* p = Vbs + kk * OUT_PV + d4 * 4;
        p[0] = f2tf_f(v.x); p[1] = f2tf_f(v.y); p[2] = f2tf_f(v.z); p[3] = f2tf_f(v.w);
    }
    __syncthreads();

    int wr = wid >> 1, wc = wid & 1;
    int m0 = wr * 16;

    float acc[4][4];
#pragma unroll
    for (int nt = 0; nt < 4; nt++)
#pragma unroll
        for (int e = 0; e < 4; e++) acc[nt][e] = 0.f;

#pragma unroll
    for (int s = 0; s < 8; s++) {
        int k0 = s * 8;
        uint32_t a0 = U(Ls[(m0 + g    ) * OUT_PL + k0 + t    ]);
        uint32_t a1 = U(Ls[(m0 + g + 8) * OUT_PL + k0 + t    ]);
        uint32_t a2 = U(Ls[(m0 + g    ) * OUT_PL + k0 + t + 4]);
        uint32_t a3 = U(Ls[(m0 + g + 8) * OUT_PL + k0 + t + 4]);
#pragma unroll
        for (int nt = 0; nt < 4; nt++) {
            int n0 = wc * 32 + nt * 8;
            uint32_t b0 = U(Vbs[(k0 + t    ) * OUT_PV + n0 + g]);
            uint32_t b1 = U(Vbs[(k0 + t + 4) * OUT_PV + n0 + g]);
            mma8(acc[nt], a0, a1, a2, a3, b0, b1);
        }
    }

    float* Og = O + (size_t)bh * N_ * D_ + (size_t)l * D_;
#pragma unroll
    for (int nt = 0; nt < 4; nt++) {
        int n0 = wc * 32 + nt * 8;
        *(float2*)(Og + (size_t)(m0 + g    ) * BB_ * D_ + n0 + 2 * t) =
            make_float2(acc[nt][0], acc[nt][1]);
        *(float2*)(Og + (size_t)(m0 + g + 8) * BB_ * D_ + n0 + 2 * t) =
            make_float2(acc[nt][2], acc[nt][3]);
    }
}

// ---------------------------------------------------------------------------
extern "C" void kernel_launch(void* const* d_in, const int* in_sizes, int n_in,
                              void* d_out, int out_size)
{
    const float* Q = (const float*)d_in[0];
    const float* K = (const float*)d_in[1];
    const float* V = (const float*)d_in[2];
    float* O = (float*)d_out;

    // Attribute sets (not stream ops; capture-safe, idempotent)
    cudaFuncSetAttribute(kl_kernel, cudaFuncAttributeMaxDynamicSharedMemorySize,
                         KL_SMEM_BYTES);
    cudaFuncSetAttribute(kr_kernel, cudaFuncAttributeMaxDynamicSharedMemorySize,
                         KR_SMEM_BYTES);

    dim3 blk(256);
    init_kbar_kernel<<<dim3(M_, BH_), blk>>>(K);
    for (int t = 0; t < NSTEPS_; t++) {
        int lastFlag = (t == NSTEPS_ - 1) ? 1 : 0;
        kl_kernel<<<dim3(BB_, BH_), blk, KL_SMEM_BYTES>>>(Q, lastFlag);
        kr_kernel<<<dim3(M_, BH_), blk, KR_SMEM_BYTES>>>(K, V, lastFlag);
    }
    out_kernel<<<dim3(BB_, BH_), blk>>>(O);
}

// round 10
// speedup vs baseline: 1.6538x; 1.6538x over previous
#include <cuda_runtime.h>
#include <cuda_fp16.h>
#include <cstdint>

// Problem constants
#define BH_   64      // B*H = 4*16
#define M_    64      // number of blocks m = N/b
#define BB_   128     // block size b
#define D_    64      // head dim
#define N_    8192
#define SCALE_ 0.125f // 1/sqrt(64)
#define EPS_   1e-6f
#define NSTEPS_ 3

// Scratch (device globals; no allocation allowed). All intermediates fp16.
__device__ __half g_Qh  [(size_t)BH_*N_*D_];       // [bh][n][d]
__device__ __half g_Kh  [(size_t)BH_*N_*D_];       // [bh][n][d]
__device__ __half g_KBAR[(size_t)BH_*BB_*M_*D_];   // [bh][l][k][d]
__device__ __half g_QBAR[(size_t)BH_*M_*BB_*D_];   // [bh][k][l][d]
__device__ __half g_LBUF[(size_t)BH_*BB_*M_*M_];   // [bh][l][i][k]
__device__ __half g_VBAR[(size_t)BH_*BB_*M_*D_];   // [bh][l][k][d]

// ---------------------------------------------------------------------------
// helpers: fp16 m16n8k16 mma + ldmatrix
// A frag (lane g=lane>>2, t=lane&3): a0={A[g][2t,2t+1]} a1={A[g+8][2t,2t+1]}
//                                    a2={A[g][2t+8,+9]} a3={A[g+8][2t+8,+9]}
// B frag: b0={B[2t][g],B[2t+1][g]}  b1={B[2t+8][g],B[2t+9][g]}  (k-major rows)
// C frag: c0=(g,2t) c1=(g,2t+1) c2=(g+8,2t) c3=(g+8,2t+1)  fp32
// ---------------------------------------------------------------------------
__device__ __forceinline__ uint32_t s2u(const void* p){
    return (uint32_t)__cvta_generic_to_shared(p);
}
__device__ __forceinline__ void ldsm4(uint32_t& r0, uint32_t& r1, uint32_t& r2,
                                      uint32_t& r3, uint32_t a){
    asm volatile("ldmatrix.sync.aligned.m8n8.x4.shared.b16 {%0,%1,%2,%3},[%4];"
        : "=r"(r0),"=r"(r1),"=r"(r2),"=r"(r3) : "r"(a));
}
__device__ __forceinline__ void ldsm4t(uint32_t& r0, uint32_t& r1, uint32_t& r2,
                                       uint32_t& r3, uint32_t a){
    asm volatile("ldmatrix.sync.aligned.m8n8.x4.trans.shared.b16 {%0,%1,%2,%3},[%4];"
        : "=r"(r0),"=r"(r1),"=r"(r2),"=r"(r3) : "r"(a));
}
__device__ __forceinline__ void mma16(float* c,
    uint32_t a0, uint32_t a1, uint32_t a2, uint32_t a3, uint32_t b0, uint32_t b1)
{
    asm volatile("mma.sync.aligned.m16n8k16.row.col.f32.f16.f16.f32 "
        "{%0,%1,%2,%3},{%4,%5,%6,%7},{%8,%9},{%0,%1,%2,%3};"
        : "+f"(c[0]), "+f"(c[1]), "+f"(c[2]), "+f"(c[3])
        : "r"(a0), "r"(a1), "r"(a2), "r"(a3), "r"(b0), "r"(b1));
}
__device__ __forceinline__ uint32_t packh2(float a, float b){
    __half2 h = __floats2half2_rn(a, b);
    return *reinterpret_cast<uint32_t*>(&h);
}

// ---------------------------------------------------------------------------
// convert Q -> half (once)
// ---------------------------------------------------------------------------
__global__ __launch_bounds__(256)
void convq_kernel(const float* __restrict__ Q)
{
    size_t base = ((size_t)blockIdx.x * 256 + threadIdx.x) * 8;
    float4 v0 = *(const float4*)(Q + base);
    float4 v1 = *(const float4*)(Q + base + 4);
    uint4 u;
    u.x = packh2(v0.x, v0.y); u.y = packh2(v0.z, v0.w);
    u.z = packh2(v1.x, v1.y); u.w = packh2(v1.z, v1.w);
    *(uint4*)(g_Qh + base) = u;
}

// ---------------------------------------------------------------------------
// K -> half + Kbar init (mean over l', broadcast over l)
// grid (M_, BH_), 256 threads
// ---------------------------------------------------------------------------
__global__ __launch_bounds__(256)
void initk_kernel(const float* __restrict__ K)
{
    int k  = blockIdx.x;
    int bh = blockIdx.y;
    int tid = threadIdx.x;
    int d = tid & 63;
    int g = tid >> 6;          // 0..3

    __shared__ float red[4][64];

    const float* Kg = K + ((size_t)bh * N_ + (size_t)k * BB_) * D_;
    __half* Khg = g_Kh + ((size_t)bh * N_ + (size_t)k * BB_) * D_;
    float s = 0.f;
    for (int lp = g; lp < BB_; lp += 4) {
        float v = Kg[(size_t)lp * D_ + d];
        s += v;
        Khg[(size_t)lp * D_ + d] = __float2half_rn(v);
    }
    red[g][d] = s;
    __syncthreads();

    __shared__ __half meanh[64];
    if (tid < 64)
        meanh[tid] = __float2half_rn(
            (red[0][tid] + red[1][tid] + red[2][tid] + red[3][tid]) * (1.0f / BB_));
    __syncthreads();

    __half mv = meanh[d];
    __half* dst = g_KBAR + ((size_t)bh * BB_ * M_ + (size_t)k) * D_;
    for (int l = g; l < BB_; l += 4)
        dst[(size_t)l * M_ * D_ + d] = mv;
}

// ---------------------------------------------------------------------------
// kl: per (bh,l): S = Q_l Kbar_l^T, L = softmax_k(scale*S),
//     Qbar = (L^T Q_l) / (w+eps).  grid (128, 64), 256 threads (8 warps 4x2)
// ---------------------------------------------------------------------------
#define KL_P 72    // half pitch (144 B rows -> conflict-free ldmatrix)

__global__ __launch_bounds__(256)
void kl_kernel(int writeL)
{
    __shared__ __half Qs[64 * KL_P];
    __shared__ __half Ks[64 * KL_P];
    __shared__ float  Ls[64 * KL_P];   // fp32 scores
    __shared__ __half Lh[64 * KL_P];   // fp16 probs
    __shared__ float  wsh[64];

    int l  = blockIdx.x;
    int bh = blockIdx.y;
    int tid = threadIdx.x;
    int lane = tid & 31, wid = tid >> 5;
    int g = lane >> 2, t = lane & 3;

    const __half* Qg = g_Qh + ((size_t)bh * N_ + l) * D_;
    for (int idx = tid; idx < 64 * 8; idx += 256) {
        int i = idx >> 3, sg = idx & 7;
        *(uint4*)(Qs + i * KL_P + sg * 8) =
            *(const uint4*)(Qg + (size_t)i * BB_ * D_ + sg * 8);
    }
    const __half* Kg = g_KBAR + ((size_t)bh * BB_ + l) * M_ * D_;
    for (int idx = tid; idx < 64 * 8; idx += 256) {
        int i = idx >> 3, sg = idx & 7;
        *(uint4*)(Ks + i * KL_P + sg * 8) = *(const uint4*)(Kg + idx * 8);
    }
    __syncthreads();

    int wr = wid >> 1, wc = wid & 1;
    int m0 = wr * 16;

    // GEMM1: S[i][k] = sum_d Q[i][d] * Kbar[k][d]
    float acc[4][4];
#pragma unroll
    for (int nt = 0; nt < 4; nt++)
#pragma unroll
        for (int e = 0; e < 4; e++) acc[nt][e] = 0.f;

#pragma unroll
    for (int s = 0; s < 4; s++) {
        int k0 = s * 16;
        uint32_t a0, a1, a2, a3;
        ldsm4(a0, a1, a2, a3,
              s2u(Qs + (m0 + (lane & 15)) * KL_P + k0 + 8 * (lane >> 4)));
#pragma unroll
        for (int p = 0; p < 2; p++) {
            int n0 = wc * 32 + p * 16;
            uint32_t b0, b1, b2, b3;
            ldsm4(b0, b1, b2, b3,
                  s2u(Ks + (n0 + (lane & 7) + 8 * (lane >> 4)) * KL_P
                         + k0 + 8 * ((lane >> 3) & 1)));
            mma16(acc[2 * p    ], a0, a1, a2, a3, b0, b1);
            mma16(acc[2 * p + 1], a0, a1, a2, a3, b2, b3);
        }
    }

    // raw scores -> Ls
#pragma unroll
    for (int nt = 0; nt < 4; nt++) {
        int n0 = wc * 32 + nt * 8 + 2 * t;
        *(float2*)(Ls + (m0 + g    ) * KL_P + n0) = make_float2(acc[nt][0], acc[nt][1]);
        *(float2*)(Ls + (m0 + g + 8) * KL_P + n0) = make_float2(acc[nt][2], acc[nt][3]);
    }
    __syncthreads();

    // softmax over k (scale folded into exp); write fp16 probs to Lh
    {
        int row = tid >> 2, q = tid & 3;
        const float* rp = Ls + row * KL_P + q * 16;
        float vv[16];
#pragma unroll
        for (int j = 0; j < 4; j++) *(float4*)(vv + 4 * j) = *(const float4*)(rp + 4 * j);
        float mx = -1e30f;
#pragma unroll
        for (int j = 0; j < 16; j++) mx = fmaxf(mx, vv[j]);
        mx = fmaxf(mx, __shfl_xor_sync(0xffffffffu, mx, 1));
        mx = fmaxf(mx, __shfl_xor_sync(0xffffffffu, mx, 2));
        float ssum = 0.f;
#pragma unroll
        for (int j = 0; j < 16; j++) { vv[j] = __expf((vv[j] - mx) * SCALE_); ssum += vv[j]; }
        ssum += __shfl_xor_sync(0xffffffffu, ssum, 1);
        ssum += __shfl_xor_sync(0xffffffffu, ssum, 2);
        float inv = 1.0f / ssum;
        __half2* op = (__half2*)(Lh + row * KL_P + q * 16);
#pragma unroll
        for (int j = 0; j < 8; j++)
            op[j] = __floats2half2_rn(vv[2 * j] * inv, vv[2 * j + 1] * inv);
    }
    __syncthreads();

    // w[k] = sum_i L[i][k]
    if (tid < 64) {
        float s = 0.f;
#pragma unroll 8
        for (int i = 0; i < 64; i++) s += __half2float(Lh[i * KL_P + tid]);
        wsh[tid] = 1.0f / (s + EPS_);
    }
    if (writeL) {
        __half* Lg = g_LBUF + ((size_t)bh * BB_ + l) * M_ * M_;
        for (int idx = tid; idx < 64 * 8; idx += 256) {
            int i = idx >> 3, sg = idx & 7;
            *(uint4*)(Lg + idx * 8) = *(uint4*)(Lh + i * KL_P + sg * 8);
        }
    }
    __syncthreads();

    // GEMM2: Qbar[kb][d] = sum_i L[i][kb] * Q[i][d]   (A = L^T via ldsm.trans)
    float acc2[4][4];
#pragma unroll
    for (int nt = 0; nt < 4; nt++)
#pragma unroll
        for (int e = 0; e < 4; e++) acc2[nt][e] = 0.f;

#pragma unroll
    for (int s = 0; s < 4; s++) {
        int i0 = s * 16;
        uint32_t a0, a1, a2, a3;
        ldsm4t(a0, a1, a2, a3,
               s2u(Lh + (i0 + (lane & 7) + 8 * (lane >> 4)) * KL_P
                      + m0 + 8 * ((lane >> 3) & 1)));
#pragma unroll
        for (int p = 0; p < 2; p++) {
            int n0 = wc * 32 + p * 16;
            uint32_t b0, b1, b2, b3;
            ldsm4t(b0, b1, b2, b3,
                   s2u(Qs + (i0 + (lane & 7) + 8 * ((lane >> 3) & 1)) * KL_P
                          + n0 + 8 * (lane >> 4)));
            mma16(acc2[2 * p    ], a0, a1, a2, a3, b0, b1);
            mma16(acc2[2 * p + 1], a0, a1, a2, a3, b2, b3);
        }
    }

    __half* Qbg = g_QBAR + (size_t)bh * M_ * BB_ * D_ + (size_t)l * D_;
    float w0 = wsh[m0 + g], w1 = wsh[m0 + g + 8];
#pragma unroll
    for (int nt = 0; nt < 4; nt++) {
        int dd = wc * 32 + nt * 8 + 2 * t;
        *(__half2*)(Qbg + (size_t)(m0 + g    ) * BB_ * D_ + dd) =
            __floats2half2_rn(acc2[nt][0] * w0, acc2[nt][1] * w0);
        *(__half2*)(Qbg + (size_t)(m0 + g + 8) * BB_ * D_ + dd) =
            __floats2half2_rn(acc2[nt][2] * w1, acc2[nt][3] * w1);
    }
}

// ---------------------------------------------------------------------------
// kr: per (bh,k): S = Qbar_k K_k^T (128x128), R = softmax(scale*S) in REGISTERS,
//     Kbar = R K_k (or Vbar = R V_k last iter).  grid (64, 64), 256 threads.
//     Each warp owns 16 full rows; P stays in registers as GEMM2 A-fragments.
// ---------------------------------------------------------------------------
#define KR_P 72

__global__ __launch_bounds__(256)
void kr_kernel(const float* __restrict__ V, int last)
{
    __shared__ __half Qbs[BB_ * KR_P];
    __shared__ __half Ks [BB_ * KR_P];   // K_k; overwritten by V_k on last iter

    int k  = blockIdx.x;
    int bh = blockIdx.y;
    int tid = threadIdx.x;
    int lane = tid & 31, wid = tid >> 5;
    int g = lane >> 2, t = lane & 3;

    const __half* Qbg = g_QBAR + ((size_t)bh * M_ + k) * BB_ * D_;
    for (int idx = tid; idx < BB_ * 8; idx += 256) {
        int r = idx >> 3, sg = idx & 7;
        *(uint4*)(Qbs + r * KR_P + sg * 8) = *(const uint4*)(Qbg + idx * 8);
    }
    const __half* Kg = g_Kh + ((size_t)bh * N_ + (size_t)k * BB_) * D_;
    for (int idx = tid; idx < BB_ * 8; idx += 256) {
        int r = idx >> 3, sg = idx & 7;
        *(uint4*)(Ks + r * KR_P + sg * 8) = *(const uint4*)(Kg + idx * 8);
    }
    __syncthreads();

    int m0 = wid * 16;

    // GEMM1: S rows m0..m0+15, all 128 cols; acc1[nt] = cols nt*8+{2t,2t+1}
    float acc1[16][4];
#pragma unroll
    for (int nt = 0; nt < 16; nt++)
#pragma unroll
        for (int e = 0; e < 4; e++) acc1[nt][e] = 0.f;

#pragma unroll
    for (int s = 0; s < 4; s++) {
        int k0 = s * 16;
        uint32_t a0, a1, a2, a3;
        ldsm4(a0, a1, a2, a3,
              s2u(Qbs + (m0 + (lane & 15)) * KR_P + k0 + 8 * (lane >> 4)));
#pragma unroll
        for (int p = 0; p < 8; p++) {
            int n0 = p * 16;
            uint32_t b0, b1, b2, b3;
            ldsm4(b0, b1, b2, b3,
                  s2u(Ks + (n0 + (lane & 7) + 8 * (lane >> 4)) * KR_P
                         + k0 + 8 * ((lane >> 3) & 1)));
            mma16(acc1[2 * p    ], a0, a1, a2, a3, b0, b1);
            mma16(acc1[2 * p + 1], a0, a1, a2, a3, b2, b3);
        }
    }

    // last iter: V replaces K in smem (GEMM1 reads done across block first)
    if (last) {
        __syncthreads();
        const float* Vg = V + ((size_t)bh * N_ + (size_t)k * BB_) * D_;
        for (int idx = tid; idx < BB_ * 16; idx += 256) {
            int r = idx >> 4, d4 = idx & 15;
            float4 v = *(const float4*)(Vg + (size_t)r * D_ + d4 * 4);
            uint2 u; u.x = packh2(v.x, v.y); u.y = packh2(v.z, v.w);
            *(uint2*)(Ks + r * KR_P + d4 * 4) = u;
        }
        __syncthreads();
    }

    // softmax over l' fully in registers (rows g and g+8; 4-lane shfl groups)
    float mx0 = -1e30f, mx1 = -1e30f;
#pragma unroll
    for (int nt = 0; nt < 16; nt++) {
        mx0 = fmaxf(mx0, fmaxf(acc1[nt][0], acc1[nt][1]));
        mx1 = fmaxf(mx1, fmaxf(acc1[nt][2], acc1[nt][3]));
    }
    mx0 = fmaxf(mx0, __shfl_xor_sync(0xffffffffu, mx0, 1));
    mx0 = fmaxf(mx0, __shfl_xor_sync(0xffffffffu, mx0, 2));
    mx1 = fmaxf(mx1, __shfl_xor_sync(0xffffffffu, mx1, 1));
    mx1 = fmaxf(mx1, __shfl_xor_sync(0xffffffffu, mx1, 2));
    float s0 = 0.f, s1 = 0.f;
#pragma unroll
    for (int nt = 0; nt < 16; nt++) {
        acc1[nt][0] = __expf((acc1[nt][0] - mx0) * SCALE_); s0 += acc1[nt][0];
        acc1[nt][1] = __expf((acc1[nt][1] - mx0) * SCALE_); s0 += acc1[nt][1];
        acc1[nt][2] = __expf((acc1[nt][2] - mx1) * SCALE_); s1 += acc1[nt][2];
        acc1[nt][3] = __expf((acc1[nt][3] - mx1) * SCALE_); s1 += acc1[nt][3];
    }
    s0 += __shfl_xor_sync(0xffffffffu, s0, 1);
    s0 += __shfl_xor_sync(0xffffffffu, s0, 2);
    s1 += __shfl_xor_sync(0xffffffffu, s1, 1);
    s1 += __shfl_xor_sync(0xffffffffu, s1, 2);
    float inv0 = 1.0f / s0, inv1 = 1.0f / s1;

    // pack probs directly as GEMM2 A-fragments (k-chunk s covers cols 16s..16s+15)
    uint32_t prob[8][4];
#pragma unroll
    for (int s = 0; s < 8; s++) {
        prob[s][0] = packh2(acc1[2*s  ][0] * inv0, acc1[2*s  ][1] * inv0);
        prob[s][1] = packh2(acc1[2*s  ][2] * inv1, acc1[2*s  ][3] * inv1);
        prob[s][2] = packh2(acc1[2*s+1][0] * inv0, acc1[2*s+1][1] * inv0);
        prob[s][3] = packh2(acc1[2*s+1][2] * inv1, acc1[2*s+1][3] * inv1);
    }

    // GEMM2: out[l][d] = sum_{l'} R[l][l'] * Op[l'][d]
    float acc2[8][4];
#pragma unroll
    for (int nt = 0; nt < 8; nt++)
#pragma unroll
        for (int e = 0; e < 4; e++) acc2[nt][e] = 0.f;

#pragma unroll
    for (int s = 0; s < 8; s++) {
        int i0 = s * 16;
#pragma unroll
        for (int p = 0; p < 4; p++) {
            int n0 = p * 16;
            uint32_t b0, b1, b2, b3;
            ldsm4t(b0, b1, b2, b3,
                   s2u(Ks + (i0 + (lane & 7) + 8 * ((lane >> 3) & 1)) * KR_P
                          + n0 + 8 * (lane >> 4)));
            mma16(acc2[2 * p    ], prob[s][0], prob[s][1], prob[s][2], prob[s][3], b0, b1);
            mma16(acc2[2 * p + 1], prob[s][0], prob[s][1], prob[s][2], prob[s][3], b2, b3);
        }
    }

    __half* dst = (last ? g_VBAR : g_KBAR) + ((size_t)bh * BB_ * M_ + k) * D_;
#pragma unroll
    for (int nt = 0; nt < 8; nt++) {
        int dd = nt * 8 + 2 * t;
        *(__half2*)(dst + (size_t)(m0 + g    ) * M_ * D_ + dd) =
            __floats2half2_rn(acc2[nt][0], acc2[nt][1]);
        *(__half2*)(dst + (size_t)(m0 + g + 8) * M_ * D_ + dd) =
            __floats2half2_rn(acc2[nt][2], acc2[nt][3]);
    }
}

// ---------------------------------------------------------------------------
// out: per (bh,l): out[i][d] = sum_kb L[i][kb] * Vbar[kb][d]
// grid (128, 64), 256 threads (8 warps 4x2)
// ---------------------------------------------------------------------------
__global__ __launch_bounds__(256)
void out_kernel(float* __restrict__ O)
{
    __shared__ __half Lsm[64 * KL_P];
    __shared__ __half Vbs[64 * KL_P];

    int l  = blockIdx.x;
    int bh = blockIdx.y;
    int tid = threadIdx.x;
    int lane = tid & 31, wid = tid >> 5;
    int g = lane >> 2, t = lane & 3;

    const __half* Lg = g_LBUF + ((size_t)bh * BB_ + l) * M_ * M_;
    for (int idx = tid; idx < 64 * 8; idx += 256) {
        int i = idx >> 3, sg = idx & 7;
        *(uint4*)(Lsm + i * KL_P + sg * 8) = *(const uint4*)(Lg + idx * 8);
    }
    const __half* Vg = g_VBAR + ((size_t)bh * BB_ + l) * M_ * D_;
    for (int idx = tid; idx < 64 * 8; idx += 256) {
        int i = idx >> 3, sg = idx & 7;
        *(uint4*)(Vbs + i * KL_P + sg * 8) = *(const uint4*)(Vg + idx * 8);
    }
    __syncthreads();

    int wr = wid >> 1, wc = wid & 1;
    int m0 = wr * 16;

    float acc[4][4];
#pragma unroll
    for (int nt = 0; nt < 4; nt++)
#pragma unroll
        for (int e = 0; e < 4; e++) acc[nt][e] = 0.f;

#pragma unroll
    for (int s = 0; s < 4; s++) {
        int k0 = s * 16;
        uint32_t a0, a1, a2, a3;
        ldsm4(a0, a1, a2, a3,
              s2u(Lsm + (m0 + (lane & 15)) * KL_P + k0 + 8 * (lane >> 4)));
#pragma unroll
        for (int p = 0; p < 2; p++) {
            int n0 = wc * 32 + p * 16;
            uint32_t b0, b1, b2, b3;
            ldsm4t(b0, b1, b2, b3,
                   s2u(Vbs + (k0 + (lane & 7) + 8 * ((lane >> 3) & 1)) * KL_P
                           + n0 + 8 * (lane >> 4)));
            mma16(acc[2 * p    ], a0, a1, a2, a3, b0, b1);
            mma16(acc[2 * p + 1], a0, a1, a2, a3, b2, b3);
        }
    }

    float* Og = O + (size_t)bh * N_ * D_ + (size_t)l * D_;
#pragma unroll
    for (int nt = 0; nt < 4; nt++) {
        int dd = wc * 32 + nt * 8 + 2 * t;
        *(float2*)(Og + (size_t)(m0 + g    ) * BB_ * D_ + dd) =
            make_float2(acc[nt][0], acc[nt][1]);
        *(float2*)(Og + (size_t)(m0 + g + 8) * BB_ * D_ + dd) =
            make_float2(acc[nt][2], acc[nt][3]);
    }
}

// ---------------------------------------------------------------------------
extern "C" void kernel_launch(void* const* d_in, const int* in_sizes, int n_in,
                              void* d_out, int out_size)
{
    const float* Q = (const float*)d_in[0];
    const float* K = (const float*)d_in[1];
    const float* V = (const float*)d_in[2];
    float* O = (float*)d_out;

    dim3 blk(256);
    convq_kernel<<<(BH_ * (size_t)N_ * D_) / (256 * 8), blk>>>(Q);
    initk_kernel<<<dim3(M_, BH_), blk>>>(K);
    for (int t = 0; t < NSTEPS_; t++) {
        int lastFlag = (t == NSTEPS_ - 1) ? 1 : 0;
        kl_kernel<<<dim3(BB_, BH_), blk>>>(lastFlag);
        kr_kernel<<<dim3(M_, BH_), blk>>>(V, lastFlag);
    }
    out_kernel<<<dim3(BB_, BH_), blk>>>(O);
}

// round 11
// speedup vs baseline: 1.9732x; 1.1932x over previous
#include <cuda_runtime.h>
#include <cuda_fp16.h>
#include <cstdint>

// Problem constants
#define BH_   64      // B*H = 4*16
#define M_    64      // number of blocks m = N/b
#define BB_   128     // block size b
#define D_    64      // head dim
#define N_    8192
#define SCALE_ 0.125f // 1/sqrt(64)
#define EPS_   1e-6f
#define NSTEPS_ 3

// Scratch (device globals; no allocation allowed). All intermediates fp16.
__device__ __half g_Qh  [(size_t)BH_*N_*D_];       // [bh][n][d]
__device__ __half g_Kh  [(size_t)BH_*N_*D_];       // [bh][n][d]
__device__ __half g_KBAR[(size_t)BH_*BB_*M_*D_];   // [bh][l][k][d]
__device__ __half g_QBAR[(size_t)BH_*M_*BB_*D_];   // [bh][k][l][d]
__device__ __half g_LBUF[(size_t)BH_*BB_*M_*M_];   // [bh][l][i][k]
__device__ __half g_VBAR[(size_t)BH_*BB_*M_*D_];   // [bh][l][k][d]

// ---------------------------------------------------------------------------
// helpers: fp16 m16n8k16 mma + ldmatrix
// ---------------------------------------------------------------------------
__device__ __forceinline__ uint32_t s2u(const void* p){
    return (uint32_t)__cvta_generic_to_shared(p);
}
__device__ __forceinline__ void ldsm4(uint32_t& r0, uint32_t& r1, uint32_t& r2,
                                      uint32_t& r3, uint32_t a){
    asm volatile("ldmatrix.sync.aligned.m8n8.x4.shared.b16 {%0,%1,%2,%3},[%4];"
        : "=r"(r0),"=r"(r1),"=r"(r2),"=r"(r3) : "r"(a));
}
__device__ __forceinline__ void ldsm4t(uint32_t& r0, uint32_t& r1, uint32_t& r2,
                                       uint32_t& r3, uint32_t a){
    asm volatile("ldmatrix.sync.aligned.m8n8.x4.trans.shared.b16 {%0,%1,%2,%3},[%4];"
        : "=r"(r0),"=r"(r1),"=r"(r2),"=r"(r3) : "r"(a));
}
__device__ __forceinline__ void mma16(float* c,
    uint32_t a0, uint32_t a1, uint32_t a2, uint32_t a3, uint32_t b0, uint32_t b1)
{
    asm volatile("mma.sync.aligned.m16n8k16.row.col.f32.f16.f16.f32 "
        "{%0,%1,%2,%3},{%4,%5,%6,%7},{%8,%9},{%0,%1,%2,%3};"
        : "+f"(c[0]), "+f"(c[1]), "+f"(c[2]), "+f"(c[3])
        : "r"(a0), "r"(a1), "r"(a2), "r"(a3), "r"(b0), "r"(b1));
}
__device__ __forceinline__ uint32_t packh2(float a, float b){
    __half2 h = __floats2half2_rn(a, b);
    return *reinterpret_cast<uint32_t*>(&h);
}

// ---------------------------------------------------------------------------
// convert Q -> half (once)
// ---------------------------------------------------------------------------
__global__ __launch_bounds__(256)
void convq_kernel(const float* __restrict__ Q)
{
    size_t base = ((size_t)blockIdx.x * 256 + threadIdx.x) * 8;
    float4 v0 = *(const float4*)(Q + base);
    float4 v1 = *(const float4*)(Q + base + 4);
    uint4 u;
    u.x = packh2(v0.x, v0.y); u.y = packh2(v0.z, v0.w);
    u.z = packh2(v1.x, v1.y); u.w = packh2(v1.z, v1.w);
    *(uint4*)(g_Qh + base) = u;
}

// ---------------------------------------------------------------------------
// K -> half + Kbar init (mean over l', broadcast over l)
// grid (M_, BH_), 256 threads
// ---------------------------------------------------------------------------
__global__ __launch_bounds__(256)
void initk_kernel(const float* __restrict__ K)
{
    int k  = blockIdx.x;
    int bh = blockIdx.y;
    int tid = threadIdx.x;
    int d = tid & 63;
    int g = tid >> 6;          // 0..3

    __shared__ float red[4][64];

    const float* Kg = K + ((size_t)bh * N_ + (size_t)k * BB_) * D_;
    __half* Khg = g_Kh + ((size_t)bh * N_ + (size_t)k * BB_) * D_;
    float s = 0.f;
    for (int lp = g; lp < BB_; lp += 4) {
        float v = Kg[(size_t)lp * D_ + d];
        s += v;
        Khg[(size_t)lp * D_ + d] = __float2half_rn(v);
    }
    red[g][d] = s;
    __syncthreads();

    __shared__ __half meanh[64];
    if (tid < 64)
        meanh[tid] = __float2half_rn(
            (red[0][tid] + red[1][tid] + red[2][tid] + red[3][tid]) * (1.0f / BB_));
    __syncthreads();

    __half mv = meanh[d];
    __half* dst = g_KBAR + ((size_t)bh * BB_ * M_ + (size_t)k) * D_;
    for (int l = g; l < BB_; l += 4)
        dst[(size_t)l * M_ * D_ + d] = mv;
}

// ---------------------------------------------------------------------------
// kl: per (bh,l): S = Q_l Kbar_l^T (64x64), L = softmax_k(scale*S) IN REGISTERS,
//     Qbar = (L^T Q_l)/(w+eps).  grid (128, 64), 128 threads (4 warps x 16 rows)
// ---------------------------------------------------------------------------
#define KL_P 72    // half pitch (144 B rows -> conflict-free ldmatrix)

__global__ __launch_bounds__(128)
void kl_kernel(int writeL)
{
    __shared__ __half Qs[64 * KL_P];
    __shared__ __half Ks[64 * KL_P];
    __shared__ __half Lh[64 * KL_P];   // fp16 probs
    __shared__ float  wsh[64];

    int l  = blockIdx.x;
    int bh = blockIdx.y;
    int tid = threadIdx.x;
    int lane = tid & 31, wid = tid >> 5;
    int g = lane >> 2, t = lane & 3;

    const __half* Qg = g_Qh + ((size_t)bh * N_ + l) * D_;
    for (int idx = tid; idx < 64 * 8; idx += 128) {
        int i = idx >> 3, sg = idx & 7;
        *(uint4*)(Qs + i * KL_P + sg * 8) =
            *(const uint4*)(Qg + (size_t)i * BB_ * D_ + sg * 8);
    }
    const __half* Kg = g_KBAR + ((size_t)bh * BB_ + l) * M_ * D_;
    for (int idx = tid; idx < 64 * 8; idx += 128) {
        int i = idx >> 3, sg = idx & 7;
        *(uint4*)(Ks + i * KL_P + sg * 8) = *(const uint4*)(Kg + idx * 8);
    }
    __syncthreads();

    int m0 = wid * 16;   // warp owns rows m0..m0+15, all 64 cols

    // GEMM1: S[i][k] = sum_d Q[i][d] * Kbar[k][d]; acc[nt] = cols nt*8+{2t,2t+1}
    float acc[8][4];
#pragma unroll
    for (int nt = 0; nt < 8; nt++)
#pragma unroll
        for (int e = 0; e < 4; e++) acc[nt][e] = 0.f;

#pragma unroll
    for (int s = 0; s < 4; s++) {
        int k0 = s * 16;
        uint32_t a0, a1, a2, a3;
        ldsm4(a0, a1, a2, a3,
              s2u(Qs + (m0 + (lane & 15)) * KL_P + k0 + 8 * (lane >> 4)));
#pragma unroll
        for (int p = 0; p < 4; p++) {
            int n0 = p * 16;
            uint32_t b0, b1, b2, b3;
            ldsm4(b0, b1, b2, b3,
                  s2u(Ks + (n0 + (lane & 7) + 8 * (lane >> 4)) * KL_P
                         + k0 + 8 * ((lane >> 3) & 1)));
            mma16(acc[2 * p    ], a0, a1, a2, a3, b0, b1);
            mma16(acc[2 * p + 1], a0, a1, a2, a3, b2, b3);
        }
    }

    // softmax over k in registers: rows g (elems 0,1) / g+8 (elems 2,3),
    // 4-lane shfl groups (t = lane&3)
    float mx0 = -1e30f, mx1 = -1e30f;
#pragma unroll
    for (int nt = 0; nt < 8; nt++) {
        mx0 = fmaxf(mx0, fmaxf(acc[nt][0], acc[nt][1]));
        mx1 = fmaxf(mx1, fmaxf(acc[nt][2], acc[nt][3]));
    }
    mx0 = fmaxf(mx0, __shfl_xor_sync(0xffffffffu, mx0, 1));
    mx0 = fmaxf(mx0, __shfl_xor_sync(0xffffffffu, mx0, 2));
    mx1 = fmaxf(mx1, __shfl_xor_sync(0xffffffffu, mx1, 1));
    mx1 = fmaxf(mx1, __shfl_xor_sync(0xffffffffu, mx1, 2));
    float s0 = 0.f, s1 = 0.f;
#pragma unroll
    for (int nt = 0; nt < 8; nt++) {
        acc[nt][0] = __expf((acc[nt][0] - mx0) * SCALE_); s0 += acc[nt][0];
        acc[nt][1] = __expf((acc[nt][1] - mx0) * SCALE_); s0 += acc[nt][1];
        acc[nt][2] = __expf((acc[nt][2] - mx1) * SCALE_); s1 += acc[nt][2];
        acc[nt][3] = __expf((acc[nt][3] - mx1) * SCALE_); s1 += acc[nt][3];
    }
    s0 += __shfl_xor_sync(0xffffffffu, s0, 1);
    s0 += __shfl_xor_sync(0xffffffffu, s0, 2);
    s1 += __shfl_xor_sync(0xffffffffu, s1, 1);
    s1 += __shfl_xor_sync(0xffffffffu, s1, 2);
    float inv0 = 1.0f / s0, inv1 = 1.0f / s1;

    // probs -> Lh (fp16), needed transposed for GEMM2 A and for w-sum
#pragma unroll
    for (int nt = 0; nt < 8; nt++) {
        int col = nt * 8 + 2 * t;
        *(__half2*)(Lh + (m0 + g    ) * KL_P + col) =
            __floats2half2_rn(acc[nt][0] * inv0, acc[nt][1] * inv0);
        *(__half2*)(Lh + (m0 + g + 8) * KL_P + col) =
            __floats2half2_rn(acc[nt][2] * inv1, acc[nt][3] * inv1);
    }
    __syncthreads();

    // w[k] = sum_i L[i][k]
    if (tid < 64) {
        float s = 0.f;
#pragma unroll 8
        for (int i = 0; i < 64; i++) s += __half2float(Lh[i * KL_P + tid]);
        wsh[tid] = 1.0f / (s + EPS_);
    }
    if (writeL) {
        __half* Lg = g_LBUF + ((size_t)bh * BB_ + l) * M_ * M_;
        for (int idx = tid; idx < 64 * 8; idx += 128) {
            int i = idx >> 3, sg = idx & 7;
            *(uint4*)(Lg + idx * 8) = *(uint4*)(Lh + i * KL_P + sg * 8);
        }
    }
    __syncthreads();

    // GEMM2: Qbar[kb][d] = sum_i L[i][kb] * Q[i][d]; warp owns kb in m0..m0+15
    float acc2[8][4];
#pragma unroll
    for (int nt = 0; nt < 8; nt++)
#pragma unroll
        for (int e = 0; e < 4; e++) acc2[nt][e] = 0.f;

#pragma unroll
    for (int s = 0; s < 4; s++) {
        int i0 = s * 16;
        uint32_t a0, a1, a2, a3;
        ldsm4t(a0, a1, a2, a3,
               s2u(Lh + (i0 + (lane & 7) + 8 * (lane >> 4)) * KL_P
                      + m0 + 8 * ((lane >> 3) & 1)));
#pragma unroll
        for (int p = 0; p < 4; p++) {
            int n0 = p * 16;
            uint32_t b0, b1, b2, b3;
            ldsm4t(b0, b1, b2, b3,
                   s2u(Qs + (i0 + (lane & 7) + 8 * ((lane >> 3) & 1)) * KL_P
                          + n0 + 8 * (lane >> 4)));
            mma16(acc2[2 * p    ], a0, a1, a2, a3, b0, b1);
            mma16(acc2[2 * p + 1], a0, a1, a2, a3, b2, b3);
        }
    }

    __half* Qbg = g_QBAR + (size_t)bh * M_ * BB_ * D_ + (size_t)l * D_;
    float w0 = wsh[m0 + g], w1 = wsh[m0 + g + 8];
#pragma unroll
    for (int nt = 0; nt < 8; nt++) {
        int dd = nt * 8 + 2 * t;
        *(__half2*)(Qbg + (size_t)(m0 + g    ) * BB_ * D_ + dd) =
            __floats2half2_rn(acc2[nt][0] * w0, acc2[nt][1] * w0);
        *(__half2*)(Qbg + (size_t)(m0 + g + 8) * BB_ * D_ + dd) =
            __floats2half2_rn(acc2[nt][2] * w1, acc2[nt][3] * w1);
    }
}

// ---------------------------------------------------------------------------
// kr: per (bh,k): S = Qbar_k K_k^T (128x128), R = softmax(scale*S) in REGISTERS,
//     Kbar = R K_k (or Vbar = R V_k last iter).  grid (64, 64), 256 threads.
//     __launch_bounds__(256,3): cap regs at ~85 -> 3 CTAs/SM for latency hiding.
// ---------------------------------------------------------------------------
#define KR_P 72

__global__ __launch_bounds__(256, 3)
void kr_kernel(const float* __restrict__ V, int last)
{
    __shared__ __half Qbs[BB_ * KR_P];
    __shared__ __half Ks [BB_ * KR_P];   // K_k; overwritten by V_k on last iter

    int k  = blockIdx.x;
    int bh = blockIdx.y;
    int tid = threadIdx.x;
    int lane = tid & 31, wid = tid >> 5;
    int g = lane >> 2, t = lane & 3;

    const __half* Qbg = g_QBAR + ((size_t)bh * M_ + k) * BB_ * D_;
    for (int idx = tid; idx < BB_ * 8; idx += 256) {
        int r = idx >> 3, sg = idx & 7;
        *(uint4*)(Qbs + r * KR_P + sg * 8) = *(const uint4*)(Qbg + idx * 8);
    }
    const __half* Kg = g_Kh + ((size_t)bh * N_ + (size_t)k * BB_) * D_;
    for (int idx = tid; idx < BB_ * 8; idx += 256) {
        int r = idx >> 3, sg = idx & 7;
        *(uint4*)(Ks + r * KR_P + sg * 8) = *(const uint4*)(Kg + idx * 8);
    }
    __syncthreads();

    int m0 = wid * 16;

    // GEMM1: S rows m0..m0+15, all 128 cols; acc1[nt] = cols nt*8+{2t,2t+1}
    float acc1[16][4];
#pragma unroll
    for (int nt = 0; nt < 16; nt++)
#pragma unroll
        for (int e = 0; e < 4; e++) acc1[nt][e] = 0.f;

#pragma unroll
    for (int s = 0; s < 4; s++) {
        int k0 = s * 16;
        uint32_t a0, a1, a2, a3;
        ldsm4(a0, a1, a2, a3,
              s2u(Qbs + (m0 + (lane & 15)) * KR_P + k0 + 8 * (lane >> 4)));
#pragma unroll
        for (int p = 0; p < 8; p++) {
            int n0 = p * 16;
            uint32_t b0, b1, b2, b3;
            ldsm4(b0, b1, b2, b3,
                  s2u(Ks + (n0 + (lane & 7) + 8 * (lane >> 4)) * KR_P
                         + k0 + 8 * ((lane >> 3) & 1)));
            mma16(acc1[2 * p    ], a0, a1, a2, a3, b0, b1);
            mma16(acc1[2 * p + 1], a0, a1, a2, a3, b2, b3);
        }
    }

    // last iter: V replaces K in smem (GEMM1 reads done across block first)
    if (last) {
        __syncthreads();
        const float* Vg = V + ((size_t)bh * N_ + (size_t)k * BB_) * D_;
        for (int idx = tid; idx < BB_ * 16; idx += 256) {
            int r = idx >> 4, d4 = idx & 15;
            float4 v = *(const float4*)(Vg + (size_t)r * D_ + d4 * 4);
            uint2 u; u.x = packh2(v.x, v.y); u.y = packh2(v.z, v.w);
            *(uint2*)(Ks + r * KR_P + d4 * 4) = u;
        }
        __syncthreads();
    }

    // softmax over l' fully in registers (rows g and g+8; 4-lane shfl groups)
    float mx0 = -1e30f, mx1 = -1e30f;
#pragma unroll
    for (int nt = 0; nt < 16; nt++) {
        mx0 = fmaxf(mx0, fmaxf(acc1[nt][0], acc1[nt][1]));
        mx1 = fmaxf(mx1, fmaxf(acc1[nt][2], acc1[nt][3]));
    }
    mx0 = fmaxf(mx0, __shfl_xor_sync(0xffffffffu, mx0, 1));
    mx0 = fmaxf(mx0, __shfl_xor_sync(0xffffffffu, mx0, 2));
    mx1 = fmaxf(mx1, __shfl_xor_sync(0xffffffffu, mx1, 1));
    mx1 = fmaxf(mx1, __shfl_xor_sync(0xffffffffu, mx1, 2));
    float s0 = 0.f, s1 = 0.f;
#pragma unroll
    for (int nt = 0; nt < 16; nt++) {
        acc1[nt][0] = __expf((acc1[nt][0] - mx0) * SCALE_); s0 += acc1[nt][0];
        acc1[nt][1] = __expf((acc1[nt][1] - mx0) * SCALE_); s0 += acc1[nt][1];
        acc1[nt][2] = __expf((acc1[nt][2] - mx1) * SCALE_); s1 += acc1[nt][2];
        acc1[nt][3] = __expf((acc1[nt][3] - mx1) * SCALE_); s1 += acc1[nt][3];
    }
    s0 += __shfl_xor_sync(0xffffffffu, s0, 1);
    s0 += __shfl_xor_sync(0xffffffffu, s0, 2);
    s1 += __shfl_xor_sync(0xffffffffu, s1, 1);
    s1 += __shfl_xor_sync(0xffffffffu, s1, 2);
    float inv0 = 1.0f / s0, inv1 = 1.0f / s1;

    // pack probs directly as GEMM2 A-fragments (k-chunk s covers cols 16s..16s+15)
    uint32_t prob[8][4];
#pragma unroll
    for (int s = 0; s < 8; s++) {
        prob[s][0] = packh2(acc1[2*s  ][0] * inv0, acc1[2*s  ][1] * inv0);
        prob[s][1] = packh2(acc1[2*s  ][2] * inv1, acc1[2*s  ][3] * inv1);
        prob[s][2] = packh2(acc1[2*s+1][0] * inv0, acc1[2*s+1][1] * inv0);
        prob[s][3] = packh2(acc1[2*s+1][2] * inv1, acc1[2*s+1][3] * inv1);
    }

    // GEMM2: out[l][d] = sum_{l'} R[l][l'] * Op[l'][d]
    float acc2[8][4];
#pragma unroll
    for (int nt = 0; nt < 8; nt++)
#pragma unroll
        for (int e = 0; e < 4; e++) acc2[nt][e] = 0.f;

#pragma unroll
    for (int s = 0; s < 8; s++) {
        int i0 = s * 16;
#pragma unroll
        for (int p = 0; p < 4; p++) {
            int n0 = p * 16;
            uint32_t b0, b1, b2, b3;
            ldsm4t(b0, b1, b2, b3,
                   s2u(Ks + (i0 + (lane & 7) + 8 * ((lane >> 3) & 1)) * KR_P
                          + n0 + 8 * (lane >> 4)));
            mma16(acc2[2 * p    ], prob[s][0], prob[s][1], prob[s][2], prob[s][3], b0, b1);
            mma16(acc2[2 * p + 1], prob[s][0], prob[s][1], prob[s][2], prob[s][3], b2, b3);
        }
    }

    __half* dst = (last ? g_VBAR : g_KBAR) + ((size_t)bh * BB_ * M_ + k) * D_;
#pragma unroll
    for (int nt = 0; nt < 8; nt++) {
        int dd = nt * 8 + 2 * t;
        *(__half2*)(dst + (size_t)(m0 + g    ) * M_ * D_ + dd) =
            __floats2half2_rn(acc2[nt][0], acc2[nt][1]);
        *(__half2*)(dst + (size_t)(m0 + g + 8) * M_ * D_ + dd) =
            __floats2half2_rn(acc2[nt][2], acc2[nt][3]);
    }
}

// ---------------------------------------------------------------------------
// out: per (bh,l): out[i][d] = sum_kb L[i][kb] * Vbar[kb][d]
// grid (128, 64), 256 threads (8 warps 4x2)
// ---------------------------------------------------------------------------
__global__ __launch_bounds__(256)
void out_kernel(float* __restrict__ O)
{
    __shared__ __half Lsm[64 * KL_P];
    __shared__ __half Vbs[64 * KL_P];

    int l  = blockIdx.x;
    int bh = blockIdx.y;
    int tid = threadIdx.x;
    int lane = tid & 31, wid = tid >> 5;
    int g = lane >> 2, t = lane & 3;

    const __half* Lg = g_LBUF + ((size_t)bh * BB_ + l) * M_ * M_;
    for (int idx = tid; idx < 64 * 8; idx += 256) {
        int i = idx >> 3, sg = idx & 7;
        *(uint4*)(Lsm + i * KL_P + sg * 8) = *(const uint4*)(Lg + idx * 8);
    }
    const __half* Vg = g_VBAR + ((size_t)bh * BB_ + l) * M_ * D_;
    for (int idx = tid; idx < 64 * 8; idx += 256) {
        int i = idx >> 3, sg = idx & 7;
        *(uint4*)(Vbs + i * KL_P + sg * 8) = *(const uint4*)(Vg + idx * 8);
    }
    __syncthreads();

    int wr = wid >> 1, wc = wid & 1;
    int m0 = wr * 16;

    float acc[4][4];
#pragma unroll
    for (int nt = 0; nt < 4; nt++)
#pragma unroll
        for (int e = 0; e < 4; e++) acc[nt][e] = 0.f;

#pragma unroll
    for (int s = 0; s < 4; s++) {
        int k0 = s * 16;
        uint32_t a0, a1, a2, a3;
        ldsm4(a0, a1, a2, a3,
              s2u(Lsm + (m0 + (lane & 15)) * KL_P + k0 + 8 * (lane >> 4)));
#pragma unroll
        for (int p = 0; p < 2; p++) {
            int n0 = wc * 32 + p * 16;
            uint32_t b0, b1, b2, b3;
            ldsm4t(b0, b1, b2, b3,
                   s2u(Vbs + (k0 + (lane & 7) + 8 * ((lane >> 3) & 1)) * KL_P
                           + n0 + 8 * (lane >> 4)));
            mma16(acc[2 * p    ], a0, a1, a2, a3, b0, b1);
            mma16(acc[2 * p + 1], a0, a1, a2, a3, b2, b3);
        }
    }

    float* Og = O + (size_t)bh * N_ * D_ + (size_t)l * D_;
#pragma unroll
    for (int nt = 0; nt < 4; nt++) {
        int dd = wc * 32 + nt * 8 + 2 * t;
        *(float2*)(Og + (size_t)(m0 + g    ) * BB_ * D_ + dd) =
            make_float2(acc[nt][0], acc[nt][1]);
        *(float2*)(Og + (size_t)(m0 + g + 8) * BB_ * D_ + dd) =
            make_float2(acc[nt][2], acc[nt][3]);
    }
}

// ---------------------------------------------------------------------------
extern "C" void kernel_launch(void* const* d_in, const int* in_sizes, int n_in,
                              void* d_out, int out_size)
{
    const float* Q = (const float*)d_in[0];
    const float* K = (const float*)d_in[1];
    const float* V = (const float*)d_in[2];
    float* O = (float*)d_out;

    dim3 blk256(256), blk128(128);
    convq_kernel<<<(BH_ * (size_t)N_ * D_) / (256 * 8), blk256>>>(Q);
    initk_kernel<<<dim3(M_, BH_), blk256>>>(K);
    for (int t = 0; t < NSTEPS_; t++) {
        int lastFlag = (t == NSTEPS_ - 1) ? 1 : 0;
        kl_kernel<<<dim3(BB_, BH_), blk128>>>(lastFlag);
        kr_kernel<<<dim3(M_, BH_), blk256>>>(V, lastFlag);
    }
    out_kernel<<<dim3(BB_, BH_), blk256>>>(O);
}

// round 13
// speedup vs baseline: 2.3484x; 1.1901x over previous
#include <cuda_runtime.h>
#include <cuda_fp16.h>
#include <cstdint>

// Problem constants
#define BH_   64      // B*H = 4*16
#define M_    64      // number of blocks m = N/b
#define BB_   128     // block size b
#define D_    64      // head dim
#define N_    8192
#define SCALE_ 0.125f // 1/sqrt(64)
#define SCALE2_ 0.18033688f   // SCALE_ * log2(e)
#define EPS_   1e-6f
#define NSTEPS_ 3

// Scratch (device globals; no allocation allowed). All intermediates fp16.
__device__ __half g_Qh  [(size_t)BH_*N_*D_];       // [bh][n][d]
__device__ __half g_Kh  [(size_t)BH_*N_*D_];       // [bh][n][d]
__device__ __half g_KBAR[(size_t)BH_*BB_*M_*D_];   // [bh][l][k][d]
__device__ __half g_QBAR[(size_t)BH_*M_*BB_*D_];   // [bh][k][l][d]
__device__ __half g_LBUF[(size_t)BH_*BB_*M_*M_];   // [bh][l][i][k]
__device__ __half g_VBAR[(size_t)BH_*BB_*M_*D_];   // [bh][l][k][d]

// ---------------------------------------------------------------------------
// helpers: fp16 m16n8k16 mma + ldmatrix + cp.async
// ---------------------------------------------------------------------------
__device__ __forceinline__ uint32_t s2u(const void* p){
    return (uint32_t)__cvta_generic_to_shared(p);
}
__device__ __forceinline__ void ldsm4(uint32_t& r0, uint32_t& r1, uint32_t& r2,
                                      uint32_t& r3, uint32_t a){
    asm volatile("ldmatrix.sync.aligned.m8n8.x4.shared.b16 {%0,%1,%2,%3},[%4];"
        : "=r"(r0),"=r"(r1),"=r"(r2),"=r"(r3) : "r"(a));
}
__device__ __forceinline__ void ldsm4t(uint32_t& r0, uint32_t& r1, uint32_t& r2,
                                       uint32_t& r3, uint32_t a){
    asm volatile("ldmatrix.sync.aligned.m8n8.x4.trans.shared.b16 {%0,%1,%2,%3},[%4];"
        : "=r"(r0),"=r"(r1),"=r"(r2),"=r"(r3) : "r"(a));
}
__device__ __forceinline__ void mma16(float* c,
    uint32_t a0, uint32_t a1, uint32_t a2, uint32_t a3, uint32_t b0, uint32_t b1)
{
    asm volatile("mma.sync.aligned.m16n8k16.row.col.f32.f16.f16.f32 "
        "{%0,%1,%2,%3},{%4,%5,%6,%7},{%8,%9},{%0,%1,%2,%3};"
        : "+f"(c[0]), "+f"(c[1]), "+f"(c[2]), "+f"(c[3])
        : "r"(a0), "r"(a1), "r"(a2), "r"(a3), "r"(b0), "r"(b1));
}
__device__ __forceinline__ uint32_t packh2(float a, float b){
    __half2 h = __floats2half2_rn(a, b);
    return *reinterpret_cast<uint32_t*>(&h);
}
__device__ __forceinline__ void cpa16(uint32_t s, const void* g){
    asm volatile("cp.async.ca.shared.global [%0], [%1], 16;"
                 :: "r"(s), "l"(g) : "memory");
}
__device__ __forceinline__ void cpa_commit_wait(){
    asm volatile("cp.async.commit_group;" ::: "memory");
    asm volatile("cp.async.wait_group 0;" ::: "memory");
}

// ---------------------------------------------------------------------------
// init: Q block -> half, K block -> half, Kbar = broadcast mean of K block
// grid (M_, BH_), 256 threads
// ---------------------------------------------------------------------------
__global__ __launch_bounds__(256)
void initqk_kernel(const float* __restrict__ Q, const float* __restrict__ K)
{
    int k  = blockIdx.x;
    int bh = blockIdx.y;
    int tid = threadIdx.x;
    int d = tid & 63;
    int g = tid >> 6;          // 0..3

    size_t off = ((size_t)bh * N_ + (size_t)k * BB_) * D_;

    // Q convert (same span as the K block)
    const float* Qg = Q + off;
    __half* Qhg = g_Qh + off;
    for (int idx = tid; idx < 1024; idx += 256) {
        float4 v0 = *(const float4*)(Qg + idx * 8);
        float4 v1 = *(const float4*)(Qg + idx * 8 + 4);
        uint4 u;
        u.x = packh2(v0.x, v0.y); u.y = packh2(v0.z, v0.w);
        u.z = packh2(v1.x, v1.y); u.w = packh2(v1.z, v1.w);
        *(uint4*)(Qhg + idx * 8) = u;
    }

    __shared__ float red[4][64];

    const float* Kg = K + off;
    __half* Khg = g_Kh + off;
    float s = 0.f;
    for (int lp = g; lp < BB_; lp += 4) {
        float v = Kg[(size_t)lp * D_ + d];
        s += v;
        Khg[(size_t)lp * D_ + d] = __float2half_rn(v);
    }
    red[g][d] = s;
    __syncthreads();

    __shared__ __half meanh[64];
    if (tid < 64)
        meanh[tid] = __float2half_rn(
            (red[0][tid] + red[1][tid] + red[2][tid] + red[3][tid]) * (1.0f / BB_));
    __syncthreads();

    __half mv = meanh[d];
    __half* dst = g_KBAR + ((size_t)bh * BB_ * M_ + (size_t)k) * D_;
    for (int l = g; l < BB_; l += 4)
        dst[(size_t)l * M_ * D_ + d] = mv;
}

// ---------------------------------------------------------------------------
// kl: per (bh,l): S = Q_l Kbar_l^T (64x64), L = softmax_k(scale*S) IN REGISTERS,
//     Qbar = (L^T Q_l)/(w+eps).  grid (128, 64), 128 threads (4 warps x 16 rows)
// ---------------------------------------------------------------------------
#define KL_P 72    // half pitch (144 B rows -> conflict-free ldmatrix)

__global__ __launch_bounds__(128)
void kl_kernel(int writeL)
{
    __shared__ __half Qs[64 * KL_P];
    __shared__ __half Ks[64 * KL_P];
    __shared__ __half Lh[64 * KL_P];
    __shared__ float  wsh[64];

    int l  = blockIdx.x;
    int bh = blockIdx.y;
    int tid = threadIdx.x;
    int lane = tid & 31, wid = tid >> 5;
    int g = lane >> 2, t = lane & 3;

    const __half* Qg = g_Qh + ((size_t)bh * N_ + l) * D_;
    for (int idx = tid; idx < 64 * 8; idx += 128) {
        int i = idx >> 3, sg = idx & 7;
        cpa16(s2u(Qs + i * KL_P + sg * 8), Qg + (size_t)i * BB_ * D_ + sg * 8);
    }
    const __half* Kg = g_KBAR + ((size_t)bh * BB_ + l) * M_ * D_;
    for (int idx = tid; idx < 64 * 8; idx += 128) {
        int i = idx >> 3, sg = idx & 7;
        cpa16(s2u(Ks + i * KL_P + sg * 8), Kg + idx * 8);
    }
    cpa_commit_wait();
    __syncthreads();

    int m0 = wid * 16;

    float acc[8][4];
#pragma unroll
    for (int nt = 0; nt < 8; nt++)
#pragma unroll
        for (int e = 0; e < 4; e++) acc[nt][e] = 0.f;

#pragma unroll
    for (int s = 0; s < 4; s++) {
        int k0 = s * 16;
        uint32_t a0, a1, a2, a3;
        ldsm4(a0, a1, a2, a3,
              s2u(Qs + (m0 + (lane & 15)) * KL_P + k0 + 8 * (lane >> 4)));
#pragma unroll
        for (int p = 0; p < 4; p++) {
            int n0 = p * 16;
            uint32_t b0, b1, b2, b3;
            ldsm4(b0, b1, b2, b3,
                  s2u(Ks + (n0 + (lane & 7) + 8 * (lane >> 4)) * KL_P
                         + k0 + 8 * ((lane >> 3) & 1)));
            mma16(acc[2 * p    ], a0, a1, a2, a3, b0, b1);
            mma16(acc[2 * p + 1], a0, a1, a2, a3, b2, b3);
        }
    }

    // softmax over k in registers: rows g / g+8; 4-lane shfl groups
    float mx0 = -1e30f, mx1 = -1e30f;
#pragma unroll
    for (int nt = 0; nt < 8; nt++) {
        mx0 = fmaxf(mx0, fmaxf(acc[nt][0], acc[nt][1]));
        mx1 = fmaxf(mx1, fmaxf(acc[nt][2], acc[nt][3]));
    }
    mx0 = fmaxf(mx0, __shfl_xor_sync(0xffffffffu, mx0, 1));
    mx0 = fmaxf(mx0, __shfl_xor_sync(0xffffffffu, mx0, 2));
    mx1 = fmaxf(mx1, __shfl_xor_sync(0xffffffffu, mx1, 1));
    mx1 = fmaxf(mx1, __shfl_xor_sync(0xffffffffu, mx1, 2));
    float nm0 = -mx0 * SCALE2_, nm1 = -mx1 * SCALE2_;
    float s0 = 0.f, s1 = 0.f;
#pragma unroll
    for (int nt = 0; nt < 8; nt++) {
        acc[nt][0] = exp2f(fmaf(acc[nt][0], SCALE2_, nm0)); s0 += acc[nt][0];
        acc[nt][1] = exp2f(fmaf(acc[nt][1], SCALE2_, nm0)); s0 += acc[nt][1];
        acc[nt][2] = exp2f(fmaf(acc[nt][2], SCALE2_, nm1)); s1 += acc[nt][2];
        acc[nt][3] = exp2f(fmaf(acc[nt][3], SCALE2_, nm1)); s1 += acc[nt][3];
    }
    s0 += __shfl_xor_sync(0xffffffffu, s0, 1);
    s0 += __shfl_xor_sync(0xffffffffu, s0, 2);
    s1 += __shfl_xor_sync(0xffffffffu, s1, 1);
    s1 += __shfl_xor_sync(0xffffffffu, s1, 2);
    float inv0 = 1.0f / s0, inv1 = 1.0f / s1;

#pragma unroll
    for (int nt = 0; nt < 8; nt++) {
        int col = nt * 8 + 2 * t;
        *(__half2*)(Lh + (m0 + g    ) * KL_P + col) =
            __floats2half2_rn(acc[nt][0] * inv0, acc[nt][1] * inv0);
        *(__half2*)(Lh + (m0 + g + 8) * KL_P + col) =
            __floats2half2_rn(acc[nt][2] * inv1, acc[nt][3] * inv1);
    }
    __syncthreads();

    if (tid < 64) {
        float s = 0.f;
#pragma unroll 8
        for (int i = 0; i < 64; i++) s += __half2float(Lh[i * KL_P + tid]);
        wsh[tid] = 1.0f / (s + EPS_);
    }
    if (writeL) {
        __half* Lg = g_LBUF + ((size_t)bh * BB_ + l) * M_ * M_;
        for (int idx = tid; idx < 64 * 8; idx += 128) {
            int i = idx >> 3, sg = idx & 7;
            *(uint4*)(Lg + idx * 8) = *(uint4*)(Lh + i * KL_P + sg * 8);
        }
    }
    __syncthreads();

    float acc2[8][4];
#pragma unroll
    for (int nt = 0; nt < 8; nt++)
#pragma unroll
        for (int e = 0; e < 4; e++) acc2[nt][e] = 0.f;

#pragma unroll
    for (int s = 0; s < 4; s++) {
        int i0 = s * 16;
        uint32_t a0, a1, a2, a3;
        ldsm4t(a0, a1, a2, a3,
               s2u(Lh + (i0 + (lane & 7) + 8 * (lane >> 4)) * KL_P
                      + m0 + 8 * ((lane >> 3) & 1)));
#pragma unroll
        for (int p = 0; p < 4; p++) {
            int n0 = p * 16;
            uint32_t b0, b1, b2, b3;
            ldsm4t(b0, b1, b2, b3,
                   s2u(Qs + (i0 + (lane & 7) + 8 * ((lane >> 3) & 1)) * KL_P
                          + n0 + 8 * (lane >> 4)));
            mma16(acc2[2 * p    ], a0, a1, a2, a3, b0, b1);
            mma16(acc2[2 * p + 1], a0, a1, a2, a3, b2, b3);
        }
    }

    __half* Qbg = g_QBAR + (size_t)bh * M_ * BB_ * D_ + (size_t)l * D_;
    float w0 = wsh[m0 + g], w1 = wsh[m0 + g + 8];
#pragma unroll
    for (int nt = 0; nt < 8; nt++) {
        int dd = nt * 8 + 2 * t;
        *(__half2*)(Qbg + (size_t)(m0 + g    ) * BB_ * D_ + dd) =
            __floats2half2_rn(acc2[nt][0] * w0, acc2[nt][1] * w0);
        *(__half2*)(Qbg + (size_t)(m0 + g + 8) * BB_ * D_ + dd) =
            __floats2half2_rn(acc2[nt][2] * w1, acc2[nt][3] * w1);
    }
}

// ---------------------------------------------------------------------------
// kr: per (bh,k): S = Qbar_k K_k^T (128x128), R = softmax(scale*S) in REGISTERS,
//     Kbar = R K_k (or Vbar = R V_k last iter).  grid (64, 64), 256 threads.
// ---------------------------------------------------------------------------
#define KR_P 72

__global__ __launch_bounds__(256, 3)
void kr_kernel(const float* __restrict__ V, int last)
{
    __shared__ __half Qbs[BB_ * KR_P];
    __shared__ __half Ks [BB_ * KR_P];   // K_k; overwritten by V_k on last iter

    int k  = blockIdx.x;
    int bh = blockIdx.y;
    int tid = threadIdx.x;
    int lane = tid & 31, wid = tid >> 5;
    int g = lane >> 2, t = lane & 3;

    const __half* Qbg = g_QBAR + ((size_t)bh * M_ + k) * BB_ * D_;
    for (int idx = tid; idx < BB_ * 8; idx += 256) {
        int r = idx >> 3, sg = idx & 7;
        cpa16(s2u(Qbs + r * KR_P + sg * 8), Qbg + idx * 8);
    }
    const __half* Kg = g_Kh + ((size_t)bh * N_ + (size_t)k * BB_) * D_;
    for (int idx = tid; idx < BB_ * 8; idx += 256) {
        int r = idx >> 3, sg = idx & 7;
        cpa16(s2u(Ks + r * KR_P + sg * 8), Kg + idx * 8);
    }
    cpa_commit_wait();
    __syncthreads();

    int m0 = wid * 16;

    // GEMM1: S rows m0..m0+15, all 128 cols; acc1[nt] = cols nt*8+{2t,2t+1}
    float acc1[16][4];
#pragma unroll
    for (int nt = 0; nt < 16; nt++)
#pragma unroll
        for (int e = 0; e < 4; e++) acc1[nt][e] = 0.f;

#pragma unroll
    for (int s = 0; s < 4; s++) {
        int k0 = s * 16;
        uint32_t a0, a1, a2, a3;
        ldsm4(a0, a1, a2, a3,
              s2u(Qbs + (m0 + (lane & 15)) * KR_P + k0 + 8 * (lane >> 4)));
#pragma unroll
        for (int p = 0; p < 8; p++) {
            int n0 = p * 16;
            uint32_t b0, b1, b2, b3;
            ldsm4(b0, b1, b2, b3,
                  s2u(Ks + (n0 + (lane & 7) + 8 * (lane >> 4)) * KR_P
                         + k0 + 8 * ((lane >> 3) & 1)));
            mma16(acc1[2 * p    ], a0, a1, a2, a3, b0, b1);
            mma16(acc1[2 * p + 1], a0, a1, a2, a3, b2, b3);
        }
    }

    // last iter: V replaces K in smem (GEMM1 reads done across block first)
    if (last) {
        __syncthreads();
        const float* Vg = V + ((size_t)bh * N_ + (size_t)k * BB_) * D_;
        for (int idx = tid; idx < BB_ * 16; idx += 256) {
            int r = idx >> 4, d4 = idx & 15;
            float4 v = *(const float4*)(Vg + (size_t)r * D_ + d4 * 4);
            uint2 u; u.x = packh2(v.x, v.y); u.y = packh2(v.z, v.w);
            *(uint2*)(Ks + r * KR_P + d4 * 4) = u;
        }
        __syncthreads();
    }

    // softmax over l' fully in registers (rows g and g+8; 4-lane shfl groups)
    float mx0 = -1e30f, mx1 = -1e30f;
#pragma unroll
    for (int nt = 0; nt < 16; nt++) {
        mx0 = fmaxf(mx0, fmaxf(acc1[nt][0], acc1[nt][1]));
        mx1 = fmaxf(mx1, fmaxf(acc1[nt][2], acc1[nt][3]));
    }
    mx0 = fmaxf(mx0, __shfl_xor_sync(0xffffffffu, mx0, 1));
    mx0 = fmaxf(mx0, __shfl_xor_sync(0xffffffffu, mx0, 2));
    mx1 = fmaxf(mx1, __shfl_xor_sync(0xffffffffu, mx1, 1));
    mx1 = fmaxf(mx1, __shfl_xor_sync(0xffffffffu, mx1, 2));
    float nm0 = -mx0 * SCALE2_, nm1 = -mx1 * SCALE2_;
    float s0 = 0.f, s1 = 0.f;
#pragma unroll
    for (int nt = 0; nt < 16; nt++) {
        acc1[nt][0] = exp2f(fmaf(acc1[nt][0], SCALE2_, nm0)); s0 += acc1[nt][0];
        acc1[nt][1] = exp2f(fmaf(acc1[nt][1], SCALE2_, nm0)); s0 += acc1[nt][1];
        acc1[nt][2] = exp2f(fmaf(acc1[nt][2], SCALE2_, nm1)); s1 += acc1[nt][2];
        acc1[nt][3] = exp2f(fmaf(acc1[nt][3], SCALE2_, nm1)); s1 += acc1[nt][3];
    }
    s0 += __shfl_xor_sync(0xffffffffu, s0, 1);
    s0 += __shfl_xor_sync(0xffffffffu, s0, 2);
    s1 += __shfl_xor_sync(0xffffffffu, s1, 1);
    s1 += __shfl_xor_sync(0xffffffffu, s1, 2);
    float inv0 = 1.0f / s0, inv1 = 1.0f / s1;

    // pack probs directly as GEMM2 A-fragments (k-chunk s covers cols 16s..16s+15)
    uint32_t prob[8][4];
#pragma unroll
    for (int s = 0; s < 8; s++) {
        prob[s][0] = packh2(acc1[2*s  ][0] * inv0, acc1[2*s  ][1] * inv0);
        prob[s][1] = packh2(acc1[2*s  ][2] * inv1, acc1[2*s  ][3] * inv1);
        prob[s][2] = packh2(acc1[2*s+1][0] * inv0, acc1[2*s+1][1] * inv0);
        prob[s][3] = packh2(acc1[2*s+1][2] * inv1, acc1[2*s+1][3] * inv1);
    }

    // GEMM2: out[l][d] = sum_{l'} R[l][l'] * Op[l'][d]
    float acc2[8][4];
#pragma unroll
    for (int nt = 0; nt < 8; nt++)
#pragma unroll
        for (int e = 0; e < 4; e++) acc2[nt][e] = 0.f;

#pragma unroll
    for (int s = 0; s < 8; s++) {
        int i0 = s * 16;
#pragma unroll
        for (int p = 0; p < 4; p++) {
            int n0 = p * 16;
            uint32_t b0, b1, b2, b3;
            ldsm4t(b0, b1, b2, b3,
                   s2u(Ks + (i0 + (lane & 7) + 8 * ((lane >> 3) & 1)) * KR_P
                          + n0 + 8 * (lane >> 4)));
            mma16(acc2[2 * p    ], prob[s][0], prob[s][1], prob[s][2], prob[s][3], b0, b1);
            mma16(acc2[2 * p + 1], prob[s][0], prob[s][1], prob[s][2], prob[s][3], b2, b3);
        }
    }

    __half* dst = (last ? g_VBAR : g_KBAR) + ((size_t)bh * BB_ * M_ + k) * D_;
#pragma unroll
    for (int nt = 0; nt < 8; nt++) {
        int dd = nt * 8 + 2 * t;
        *(__half2*)(dst + (size_t)(m0 + g    ) * M_ * D_ + dd) =
            __floats2half2_rn(acc2[nt][0], acc2[nt][1]);
        *(__half2*)(dst + (size_t)(m0 + g + 8) * M_ * D_ + dd) =
            __floats2half2_rn(acc2[nt][2], acc2[nt][3]);
    }
}

// ---------------------------------------------------------------------------
// out: per (bh,l): out[i][d] = sum_kb L[i][kb] * Vbar[kb][d]
// grid (128, 64), 256 threads (8 warps 4x2)
// ---------------------------------------------------------------------------
__global__ __launch_bounds__(256)
void out_kernel(float* __restrict__ O)
{
    __shared__ __half Lsm[64 * KL_P];
    __shared__ __half Vbs[64 * KL_P];

    int l  = blockIdx.x;
    int bh = blockIdx.y;
    int tid = threadIdx.x;
    int lane = tid & 31, wid = tid >> 5;
    int g = lane >> 2, t = lane & 3;

    const __half* Lg = g_LBUF + ((size_t)bh * BB_ + l) * M_ * M_;
    for (int idx = tid; idx < 64 * 8; idx += 256) {
        int i = idx >> 3, sg = idx & 7;
        cpa16(s2u(Lsm + i * KL_P + sg * 8), Lg + idx * 8);
    }
    const __half* Vg = g_VBAR + ((size_t)bh * BB_ + l) * M_ * D_;
    for (int idx = tid; idx < 64 * 8; idx += 256) {
        int i = idx >> 3, sg = idx & 7;
        cpa16(s2u(Vbs + i * KL_P + sg * 8), Vg + idx * 8);
    }
    cpa_commit_wait();
    __syncthreads();

    int wr = wid >> 1, wc = wid & 1;
    int m0 = wr * 16;

    float acc[4][4];
#pragma unroll
    for (int nt = 0; nt < 4; nt++)
#pragma unroll
        for (int e = 0; e < 4; e++) acc[nt][e] = 0.f;

#pragma unroll
    for (int s = 0; s < 4; s++) {
        int k0 = s * 16;
        uint32_t a0, a1, a2, a3;
        ldsm4(a0, a1, a2, a3,
              s2u(Lsm + (m0 + (lane & 15)) * KL_P + k0 + 8 * (lane >> 4)));
#pragma unroll
        for (int p = 0; p < 2; p++) {
            int n0 = wc * 32 + p * 16;
            uint32_t b0, b1, b2, b3;
            ldsm4t(b0, b1, b2, b3,
                   s2u(Vbs + (k0 + (lane & 7) + 8 * ((lane >> 3) & 1)) * KL_P
                           + n0 + 8 * (lane >> 4)));
            mma16(acc[2 * p    ], a0, a1, a2, a3, b0, b1);
            mma16(acc[2 * p + 1], a0, a1, a2, a3, b2, b3);
        }
    }

    float* Og = O + (size_t)bh * N_ * D_ + (size_t)l * D_;
#pragma unroll
    for (int nt = 0; nt < 4; nt++) {
        int dd = wc * 32 + nt * 8 + 2 * t;
        *(float2*)(Og + (size_t)(m0 + g    ) * BB_ * D_ + dd) =
            make_float2(acc[nt][0], acc[nt][1]);
        *(float2*)(Og + (size_t)(m0 + g + 8) * BB_ * D_ + dd) =
            make_float2(acc[nt][2], acc[nt][3]);
    }
}

// ---------------------------------------------------------------------------
extern "C" void kernel_launch(void* const* d_in, const int* in_sizes, int n_in,
                              void* d_out, int out_size)
{
    const float* Q = (const float*)d_in[0];
    const float* K = (const float*)d_in[1];
    const float* V = (const float*)d_in[2];
    float* O = (float*)d_out;

    dim3 blk256(256), blk128(128);
    initqk_kernel<<<dim3(M_, BH_), blk256>>>(Q, K);
    for (int t = 0; t < NSTEPS_; t++) {
        int lastFlag = (t == NSTEPS_ - 1) ? 1 : 0;
        kl_kernel<<<dim3(BB_, BH_), blk128>>>(lastFlag);
        kr_kernel<<<dim3(M_, BH_), blk256>>>(V, lastFlag);
    }
    out_kernel<<<dim3(BB_, BH_), blk256>>>(O);
}

// round 14
// speedup vs baseline: 2.3503x; 1.0008x over previous
#include <cuda_runtime.h>
#include <cuda_fp16.h>
#include <cstdint>

// Problem constants
#define BH_   64      // B*H = 4*16
#define M_    64      // number of blocks m = N/b
#define BB_   128     // block size b
#define D_    64      // head dim
#define N_    8192
#define SCALE_ 0.125f // 1/sqrt(64)
#define SCALE2_ 0.18033688f   // SCALE_ * log2(e)
#define EPS_   1e-6f
#define NSTEPS_ 3

// Scratch (device globals; no allocation allowed). All intermediates fp16.
__device__ __half g_Qh  [(size_t)BH_*N_*D_];       // [bh][n][d]
__device__ __half g_Kh  [(size_t)BH_*N_*D_];       // [bh][n][d]
__device__ __half g_KBAR[(size_t)BH_*BB_*M_*D_];   // [bh][l][k][d]
__device__ __half g_QBAR[(size_t)BH_*M_*BB_*D_];   // [bh][k][l][d]
__device__ __half g_LBUF[(size_t)BH_*BB_*M_*M_];   // [bh][l][i][k]
__device__ __half g_VBAR[(size_t)BH_*BB_*M_*D_];   // [bh][l][k][d]

// ---------------------------------------------------------------------------
// helpers: fp16 m16n8k16 mma + ldmatrix + cp.async
// ---------------------------------------------------------------------------
__device__ __forceinline__ uint32_t s2u(const void* p){
    return (uint32_t)__cvta_generic_to_shared(p);
}
__device__ __forceinline__ void ldsm4(uint32_t& r0, uint32_t& r1, uint32_t& r2,
                                      uint32_t& r3, uint32_t a){
    asm volatile("ldmatrix.sync.aligned.m8n8.x4.shared.b16 {%0,%1,%2,%3},[%4];"
        : "=r"(r0),"=r"(r1),"=r"(r2),"=r"(r3) : "r"(a));
}
__device__ __forceinline__ void ldsm4t(uint32_t& r0, uint32_t& r1, uint32_t& r2,
                                       uint32_t& r3, uint32_t a){
    asm volatile("ldmatrix.sync.aligned.m8n8.x4.trans.shared.b16 {%0,%1,%2,%3},[%4];"
        : "=r"(r0),"=r"(r1),"=r"(r2),"=r"(r3) : "r"(a));
}
__device__ __forceinline__ void ldsm2t(uint32_t& r0, uint32_t& r1, uint32_t a){
    asm volatile("ldmatrix.sync.aligned.m8n8.x2.trans.shared.b16 {%0,%1},[%2];"
        : "=r"(r0),"=r"(r1) : "r"(a));
}
__device__ __forceinline__ void mma16(float* c,
    uint32_t a0, uint32_t a1, uint32_t a2, uint32_t a3, uint32_t b0, uint32_t b1)
{
    asm volatile("mma.sync.aligned.m16n8k16.row.col.f32.f16.f16.f32 "
        "{%0,%1,%2,%3},{%4,%5,%6,%7},{%8,%9},{%0,%1,%2,%3};"
        : "+f"(c[0]), "+f"(c[1]), "+f"(c[2]), "+f"(c[3])
        : "r"(a0), "r"(a1), "r"(a2), "r"(a3), "r"(b0), "r"(b1));
}
__device__ __forceinline__ uint32_t packh2(float a, float b){
    __half2 h = __floats2half2_rn(a, b);
    return *reinterpret_cast<uint32_t*>(&h);
}
__device__ __forceinline__ void cpa16(uint32_t s, const void* g){
    asm volatile("cp.async.ca.shared.global [%0], [%1], 16;"
                 :: "r"(s), "l"(g) : "memory");
}
__device__ __forceinline__ void cpa_commit(){
    asm volatile("cp.async.commit_group;" ::: "memory");
}
__device__ __forceinline__ void cpa_wait0(){
    asm volatile("cp.async.wait_group 0;" ::: "memory");
}
__device__ __forceinline__ void cpa_wait1(){
    asm volatile("cp.async.wait_group 1;" ::: "memory");
}

// ---------------------------------------------------------------------------
// init: Q block -> half, K block -> half, Kbar = broadcast mean of K block
// grid (M_, BH_), 256 threads
// ---------------------------------------------------------------------------
__global__ __launch_bounds__(256)
void initqk_kernel(const float* __restrict__ Q, const float* __restrict__ K)
{
    int k  = blockIdx.x;
    int bh = blockIdx.y;
    int tid = threadIdx.x;
    int d = tid & 63;
    int g = tid >> 6;          // 0..3

    size_t off = ((size_t)bh * N_ + (size_t)k * BB_) * D_;

    const float* Qg = Q + off;
    __half* Qhg = g_Qh + off;
    for (int idx = tid; idx < 1024; idx += 256) {
        float4 v0 = *(const float4*)(Qg + idx * 8);
        float4 v1 = *(const float4*)(Qg + idx * 8 + 4);
        uint4 u;
        u.x = packh2(v0.x, v0.y); u.y = packh2(v0.z, v0.w);
        u.z = packh2(v1.x, v1.y); u.w = packh2(v1.z, v1.w);
        *(uint4*)(Qhg + idx * 8) = u;
    }

    __shared__ float red[4][64];

    const float* Kg = K + off;
    __half* Khg = g_Kh + off;
    float s = 0.f;
    for (int lp = g; lp < BB_; lp += 4) {
        float v = Kg[(size_t)lp * D_ + d];
        s += v;
        Khg[(size_t)lp * D_ + d] = __float2half_rn(v);
    }
    red[g][d] = s;
    __syncthreads();

    __shared__ __half meanh[64];
    if (tid < 64)
        meanh[tid] = __float2half_rn(
            (red[0][tid] + red[1][tid] + red[2][tid] + red[3][tid]) * (1.0f / BB_));
    __syncthreads();

    __half mv = meanh[d];
    __half* dst = g_KBAR + ((size_t)bh * BB_ * M_ + (size_t)k) * D_;
    for (int l = g; l < BB_; l += 4)
        dst[(size_t)l * M_ * D_ + d] = mv;
}

// ---------------------------------------------------------------------------
// kl: per (bh,l): S = Q_l Kbar_l^T (64x64), L = softmax_k(scale*S) IN REGISTERS,
//     Qbar = (L^T Q_l)/(w+eps) with w computed by an extra ones-column MMA.
//     grid (128, 64), 128 threads (4 warps x 16 rows)
// ---------------------------------------------------------------------------
#define KL_P 72    // half pitch (144 B rows -> conflict-free ldmatrix)

__global__ __launch_bounds__(128, 8)
void kl_kernel(int writeL)
{
    __shared__ __half Qs[64 * KL_P];
    __shared__ __half Ks[64 * KL_P];
    __shared__ __half Lh[64 * KL_P];

    int l  = blockIdx.x;
    int bh = blockIdx.y;
    int tid = threadIdx.x;
    int lane = tid & 31, wid = tid >> 5;
    int g = lane >> 2, t = lane & 3;

    const __half* Qg = g_Qh + ((size_t)bh * N_ + l) * D_;
    for (int idx = tid; idx < 64 * 8; idx += 128) {
        int i = idx >> 3, sg = idx & 7;
        cpa16(s2u(Qs + i * KL_P + sg * 8), Qg + (size_t)i * BB_ * D_ + sg * 8);
    }
    const __half* Kg = g_KBAR + ((size_t)bh * BB_ + l) * M_ * D_;
    for (int idx = tid; idx < 64 * 8; idx += 128) {
        int i = idx >> 3, sg = idx & 7;
        cpa16(s2u(Ks + i * KL_P + sg * 8), Kg + idx * 8);
    }
    // ones column in Qs padding: col 64 = 1.0h, cols 65-71 = 0 (w via MMA)
    if (tid < 64)
        *(uint4*)(Qs + tid * KL_P + 64) = make_uint4(0x00003C00u, 0u, 0u, 0u);
    cpa_commit();
    cpa_wait0();
    __syncthreads();

    int m0 = wid * 16;

    // GEMM1: S[i][k] = sum_d Q[i][d] * Kbar[k][d]; acc[nt] = cols nt*8+{2t,2t+1}
    float acc[8][4];
#pragma unroll
    for (int nt = 0; nt < 8; nt++)
#pragma unroll
        for (int e = 0; e < 4; e++) acc[nt][e] = 0.f;

#pragma unroll
    for (int s = 0; s < 4; s++) {
        int k0 = s * 16;
        uint32_t a0, a1, a2, a3;
        ldsm4(a0, a1, a2, a3,
              s2u(Qs + (m0 + (lane & 15)) * KL_P + k0 + 8 * (lane >> 4)));
#pragma unroll
        for (int p = 0; p < 4; p++) {
            int n0 = p * 16;
            uint32_t b0, b1, b2, b3;
            ldsm4(b0, b1, b2, b3,
                  s2u(Ks + (n0 + (lane & 7) + 8 * (lane >> 4)) * KL_P
                         + k0 + 8 * ((lane >> 3) & 1)));
            mma16(acc[2 * p    ], a0, a1, a2, a3, b0, b1);
            mma16(acc[2 * p + 1], a0, a1, a2, a3, b2, b3);
        }
    }

    // softmax over k in registers: rows g / g+8; 4-lane shfl groups
    float mx0 = -1e30f, mx1 = -1e30f;
#pragma unroll
    for (int nt = 0; nt < 8; nt++) {
        mx0 = fmaxf(mx0, fmaxf(acc[nt][0], acc[nt][1]));
        mx1 = fmaxf(mx1, fmaxf(acc[nt][2], acc[nt][3]));
    }
    mx0 = fmaxf(mx0, __shfl_xor_sync(0xffffffffu, mx0, 1));
    mx0 = fmaxf(mx0, __shfl_xor_sync(0xffffffffu, mx0, 2));
    mx1 = fmaxf(mx1, __shfl_xor_sync(0xffffffffu, mx1, 1));
    mx1 = fmaxf(mx1, __shfl_xor_sync(0xffffffffu, mx1, 2));
    float nm0 = -mx0 * SCALE2_, nm1 = -mx1 * SCALE2_;
    float s0 = 0.f, s1 = 0.f;
#pragma unroll
    for (int nt = 0; nt < 8; nt++) {
        acc[nt][0] = exp2f(fmaf(acc[nt][0], SCALE2_, nm0)); s0 += acc[nt][0];
        acc[nt][1] = exp2f(fmaf(acc[nt][1], SCALE2_, nm0)); s0 += acc[nt][1];
        acc[nt][2] = exp2f(fmaf(acc[nt][2], SCALE2_, nm1)); s1 += acc[nt][2];
        acc[nt][3] = exp2f(fmaf(acc[nt][3], SCALE2_, nm1)); s1 += acc[nt][3];
    }
    s0 += __shfl_xor_sync(0xffffffffu, s0, 1);
    s0 += __shfl_xor_sync(0xffffffffu, s0, 2);
    s1 += __shfl_xor_sync(0xffffffffu, s1, 1);
    s1 += __shfl_xor_sync(0xffffffffu, s1, 2);
    float inv0 = 1.0f / s0, inv1 = 1.0f / s1;

#pragma unroll
    for (int nt = 0; nt < 8; nt++) {
        int col = nt * 8 + 2 * t;
        *(__half2*)(Lh + (m0 + g    ) * KL_P + col) =
            __floats2half2_rn(acc[nt][0] * inv0, acc[nt][1] * inv0);
        *(__half2*)(Lh + (m0 + g + 8) * KL_P + col) =
            __floats2half2_rn(acc[nt][2] * inv1, acc[nt][3] * inv1);
    }
    __syncthreads();

    if (writeL) {
        __half* Lg = g_LBUF + ((size_t)bh * BB_ + l) * M_ * M_;
        for (int idx = tid; idx < 64 * 8; idx += 128) {
            int i = idx >> 3, sg = idx & 7;
            *(uint4*)(Lg + idx * 8) = *(uint4*)(Lh + i * KL_P + sg * 8);
        }
    }

    // GEMM2: Qbar[kb][d] = sum_i L[i][kb] * Q[i][d]; warp owns kb in m0..m0+15.
    // Extra ones-column tile (Qs cols 64-71) yields w[kb] in accw col 64.
    float acc2[8][4];
    float accw[4] = {0.f, 0.f, 0.f, 0.f};
#pragma unroll
    for (int nt = 0; nt < 8; nt++)
#pragma unroll
        for (int e = 0; e < 4; e++) acc2[nt][e] = 0.f;

#pragma unroll
    for (int s = 0; s < 4; s++) {
        int i0 = s * 16;
        uint32_t a0, a1, a2, a3;
        ldsm4t(a0, a1, a2, a3,
               s2u(Lh + (i0 + (lane & 7) + 8 * (lane >> 4)) * KL_P
                      + m0 + 8 * ((lane >> 3) & 1)));
#pragma unroll
        for (int p = 0; p < 4; p++) {
            int n0 = p * 16;
            uint32_t b0, b1, b2, b3;
            ldsm4t(b0, b1, b2, b3,
                   s2u(Qs + (i0 + (lane & 7) + 8 * ((lane >> 3) & 1)) * KL_P
                          + n0 + 8 * (lane >> 4)));
            mma16(acc2[2 * p    ], a0, a1, a2, a3, b0, b1);
            mma16(acc2[2 * p + 1], a0, a1, a2, a3, b2, b3);
        }
        // ones tile: cols 64-71
        uint32_t w0, w1;
        ldsm2t(w0, w1,
               s2u(Qs + (i0 + (lane & 7) + 8 * ((lane >> 3) & 1)) * KL_P + 64));
        mma16(accw, a0, a1, a2, a3, w0, w1);
    }

    // w sits in output col 64 -> t=0 lanes; broadcast within each quad
    float wr0 = __shfl_sync(0xffffffffu, accw[0], lane & 28);
    float wr1 = __shfl_sync(0xffffffffu, accw[2], lane & 28);
    float w0 = 1.0f / (wr0 + EPS_), w1 = 1.0f / (wr1 + EPS_);

    __half* Qbg = g_QBAR + (size_t)bh * M_ * BB_ * D_ + (size_t)l * D_;
#pragma unroll
    for (int nt = 0; nt < 8; nt++) {
        int dd = nt * 8 + 2 * t;
        *(__half2*)(Qbg + (size_t)(m0 + g    ) * BB_ * D_ + dd) =
            __floats2half2_rn(acc2[nt][0] * w0, acc2[nt][1] * w0);
        *(__half2*)(Qbg + (size_t)(m0 + g + 8) * BB_ * D_ + dd) =
            __floats2half2_rn(acc2[nt][2] * w1, acc2[nt][3] * w1);
    }
}

// ---------------------------------------------------------------------------
// kr: per (bh,k): S = Qbar_k K_k^T (128x128), R = softmax(scale*S) in REGISTERS,
//     Kbar = R K_k (or Vbar = R V_k last iter).  grid (64, 64), 256 threads.
//     V prefetched via a second cp.async group into fp32 staging smem.
// ---------------------------------------------------------------------------
#define KR_P 72

__global__ __launch_bounds__(256, 3)
void kr_kernel(const float* __restrict__ V, int last)
{
    __shared__ __half Qbs[BB_ * KR_P];
    __shared__ __half Ks [BB_ * KR_P];   // K_k; overwritten by V_k on last iter
    __shared__ float  Vf [BB_ * D_];     // fp32 V staging (last iter only)

    int k  = blockIdx.x;
    int bh = blockIdx.y;
    int tid = threadIdx.x;
    int lane = tid & 31, wid = tid >> 5;
    int g = lane >> 2, t = lane & 3;

    const __half* Qbg = g_QBAR + ((size_t)bh * M_ + k) * BB_ * D_;
    for (int idx = tid; idx < BB_ * 8; idx += 256) {
        int r = idx >> 3, sg = idx & 7;
        cpa16(s2u(Qbs + r * KR_P + sg * 8), Qbg + idx * 8);
    }
    const __half* Kg = g_Kh + ((size_t)bh * N_ + (size_t)k * BB_) * D_;
    for (int idx = tid; idx < BB_ * 8; idx += 256) {
        int r = idx >> 3, sg = idx & 7;
        cpa16(s2u(Ks + r * KR_P + sg * 8), Kg + idx * 8);
    }
    cpa_commit();
    if (last) {
        const float* Vg = V + ((size_t)bh * N_ + (size_t)k * BB_) * D_;
        for (int idx = tid; idx < BB_ * 16; idx += 256)
            cpa16(s2u(Vf + idx * 4), Vg + idx * 4);
        cpa_commit();
        cpa_wait1();           // Qbs/Ks done; V may still be in flight
    } else {
        cpa_wait0();
    }
    __syncthreads();

    int m0 = wid * 16;

    // GEMM1: S rows m0..m0+15, all 128 cols; acc1[nt] = cols nt*8+{2t,2t+1}
    float acc1[16][4];
#pragma unroll
    for (int nt = 0; nt < 16; nt++)
#pragma unroll
        for (int e = 0; e < 4; e++) acc1[nt][e] = 0.f;

#pragma unroll
    for (int s = 0; s < 4; s++) {
        int k0 = s * 16;
        uint32_t a0, a1, a2, a3;
        ldsm4(a0, a1, a2, a3,
              s2u(Qbs + (m0 + (lane & 15)) * KR_P + k0 + 8 * (lane >> 4)));
#pragma unroll
        for (int p = 0; p < 8; p++) {
            int n0 = p * 16;
            uint32_t b0, b1, b2, b3;
            ldsm4(b0, b1, b2, b3,
                  s2u(Ks + (n0 + (lane & 7) + 8 * (lane >> 4)) * KR_P
                         + k0 + 8 * ((lane >> 3) & 1)));
            mma16(acc1[2 * p    ], a0, a1, a2, a3, b0, b1);
            mma16(acc1[2 * p + 1], a0, a1, a2, a3, b2, b3);
        }
    }

    // last iter: V (already staged in smem fp32) replaces K in Ks
    if (last) {
        __syncthreads();       // all warps done reading Ks
        cpa_wait0();           // V staging complete
        for (int idx = tid; idx < BB_ * 16; idx += 256) {
            int r = idx >> 4, d4 = idx & 15;
            float4 v = *(const float4*)(Vf + r * D_ + d4 * 4);
            uint2 u; u.x = packh2(v.x, v.y); u.y = packh2(v.z, v.w);
            *(uint2*)(Ks + r * KR_P + d4 * 4) = u;
        }
        __syncthreads();
    }

    // softmax over l' fully in registers (rows g and g+8; 4-lane shfl groups)
    float mx0 = -1e30f, mx1 = -1e30f;
#pragma unroll
    for (int nt = 0; nt < 16; nt++) {
        mx0 = fmaxf(mx0, fmaxf(acc1[nt][0], acc1[nt][1]));
        mx1 = fmaxf(mx1, fmaxf(acc1[nt][2], acc1[nt][3]));
    }
    mx0 = fmaxf(mx0, __shfl_xor_sync(0xffffffffu, mx0, 1));
    mx0 = fmaxf(mx0, __shfl_xor_sync(0xffffffffu, mx0, 2));
    mx1 = fmaxf(mx1, __shfl_xor_sync(0xffffffffu, mx1, 1));
    mx1 = fmaxf(mx1, __shfl_xor_sync(0xffffffffu, mx1, 2));
    float nm0 = -mx0 * SCALE2_, nm1 = -mx1 * SCALE2_;
    float s0 = 0.f, s1 = 0.f;
#pragma unroll
    for (int nt = 0; nt < 16; nt++) {
        acc1[nt][0] = exp2f(fmaf(acc1[nt][0], SCALE2_, nm0)); s0 += acc1[nt][0];
        acc1[nt][1] = exp2f(fmaf(acc1[nt][1], SCALE2_, nm0)); s0 += acc1[nt][1];
        acc1[nt][2] = exp2f(fmaf(acc1[nt][2], SCALE2_, nm1)); s1 += acc1[nt][2];
        acc1[nt][3] = exp2f(fmaf(acc1[nt][3], SCALE2_, nm1)); s1 += acc1[nt][3];
    }
    s0 += __shfl_xor_sync(0xffffffffu, s0, 1);
    s0 += __shfl_xor_sync(0xffffffffu, s0, 2);
    s1 += __shfl_xor_sync(0xffffffffu, s1, 1);
    s1 += __shfl_xor_sync(0xffffffffu, s1, 2);
    float inv0 = 1.0f / s0, inv1 = 1.0f / s1;

    // pack probs directly as GEMM2 A-fragments (k-chunk s covers cols 16s..16s+15)
    uint32_t prob[8][4];
#pragma unroll
    for (int s = 0; s < 8; s++) {
        prob[s][0] = packh2(acc1[2*s  ][0] * inv0, acc1[2*s  ][1] * inv0);
        prob[s][1] = packh2(acc1[2*s  ][2] * inv1, acc1[2*s  ][3] * inv1);
        prob[s][2] = packh2(acc1[2*s+1][0] * inv0, acc1[2*s+1][1] * inv0);
        prob[s][3] = packh2(acc1[2*s+1][2] * inv1, acc1[2*s+1][3] * inv1);
    }

    // GEMM2: out[l][d] = sum_{l'} R[l][l'] * Op[l'][d]
    float acc2[8][4];
#pragma unroll
    for (int nt = 0; nt < 8; nt++)
#pragma unroll
        for (int e = 0; e < 4; e++) acc2[nt][e] = 0.f;

#pragma unroll
    for (int s = 0; s < 8; s++) {
        int i0 = s * 16;
#pragma unroll
        for (int p = 0; p < 4; p++) {
            int n0 = p * 16;
            uint32_t b0, b1, b2, b3;
            ldsm4t(b0, b1, b2, b3,
                   s2u(Ks + (i0 + (lane & 7) + 8 * ((lane >> 3) & 1)) * KR_P
                          + n0 + 8 * (lane >> 4)));
            mma16(acc2[2 * p    ], prob[s][0], prob[s][1], prob[s][2], prob[s][3], b0, b1);
            mma16(acc2[2 * p + 1], prob[s][0], prob[s][1], prob[s][2], prob[s][3], b2, b3);
        }
    }

    __half* dst = (last ? g_VBAR : g_KBAR) + ((size_t)bh * BB_ * M_ + k) * D_;
#pragma unroll
    for (int nt = 0; nt < 8; nt++) {
        int dd = nt * 8 + 2 * t;
        *(__half2*)(dst + (size_t)(m0 + g    ) * M_ * D_ + dd) =
            __floats2half2_rn(acc2[nt][0], acc2[nt][1]);
        *(__half2*)(dst + (size_t)(m0 + g + 8) * M_ * D_ + dd) =
            __floats2half2_rn(acc2[nt][2], acc2[nt][3]);
    }
}

// ---------------------------------------------------------------------------
// out: per (bh,l): out[i][d] = sum_kb L[i][kb] * Vbar[kb][d]
// grid (128, 64), 256 threads (8 warps 4x2)
// ---------------------------------------------------------------------------
__global__ __launch_bounds__(256)
void out_kernel(float* __restrict__ O)
{
    __shared__ __half Lsm[64 * KL_P];
    __shared__ __half Vbs[64 * KL_P];

    int l  = blockIdx.x;
    int bh = blockIdx.y;
    int tid = threadIdx.x;
    int lane = tid & 31, wid = tid >> 5;
    int g = lane >> 2, t = lane & 3;

    const __half* Lg = g_LBUF + ((size_t)bh * BB_ + l) * M_ * M_;
    for (int idx = tid; idx < 64 * 8; idx += 256) {
        int i = idx >> 3, sg = idx & 7;
        cpa16(s2u(Lsm + i * KL_P + sg * 8), Lg + idx * 8);
    }
    const __half* Vg = g_VBAR + ((size_t)bh * BB_ + l) * M_ * D_;
    for (int idx = tid; idx < 64 * 8; idx += 256) {
        int i = idx >> 3, sg = idx & 7;
        cpa16(s2u(Vbs + i * KL_P + sg * 8), Vg + idx * 8);
    }
    cpa_commit();
    cpa_wait0();
    __syncthreads();

    int wr = wid >> 1, wc = wid & 1;
    int m0 = wr * 16;

    float acc[4][4];
#pragma unroll
    for (int nt = 0; nt < 4; nt++)
#pragma unroll
        for (int e = 0; e < 4; e++) acc[nt][e] = 0.f;

#pragma unroll
    for (int s = 0; s < 4; s++) {
        int k0 = s * 16;
        uint32_t a0, a1, a2, a3;
        ldsm4(a0, a1, a2, a3,
              s2u(Lsm + (m0 + (lane & 15)) * KL_P + k0 + 8 * (lane >> 4)));
#pragma unroll
        for (int p = 0; p < 2; p++) {
            int n0 = wc * 32 + p * 16;
            uint32_t b0, b1, b2, b3;
            ldsm4t(b0, b1, b2, b3,
                   s2u(Vbs + (k0 + (lane & 7) + 8 * ((lane >> 3) & 1)) * KL_P
                           + n0 + 8 * (lane >> 4)));
            mma16(acc[2 * p    ], a0, a1, a2, a3, b0, b1);
            mma16(acc[2 * p + 1], a0, a1, a2, a3, b2, b3);
        }
    }

    float* Og = O + (size_t)bh * N_ * D_ + (size_t)l * D_;
#pragma unroll
    for (int nt = 0; nt < 4; nt++) {
        int dd = wc * 32 + nt * 8 + 2 * t;
        *(float2*)(Og + (size_t)(m0 + g    ) * BB_ * D_ + dd) =
            make_float2(acc[nt][0], acc[nt][1]);
        *(float2*)(Og + (size_t)(m0 + g + 8) * BB_ * D_ + dd) =
            make_float2(acc[nt][2], acc[nt][3]);
    }
}

// ---------------------------------------------------------------------------
extern "C" void kernel_launch(void* const* d_in, const int* in_sizes, int n_in,
                              void* d_out, int out_size)
{
    const float* Q = (const float*)d_in[0];
    const float* K = (const float*)d_in[1];
    const float* V = (const float*)d_in[2];
    float* O = (float*)d_out;

    dim3 blk256(256), blk128(128);
    initqk_kernel<<<dim3(M_, BH_), blk256>>>(Q, K);
    for (int t = 0; t < NSTEPS_; t++) {
        int lastFlag = (t == NSTEPS_ - 1) ? 1 : 0;
        kl_kernel<<<dim3(BB_, BH_), blk128>>>(lastFlag);
        kr_kernel<<<dim3(M_, BH_), blk256>>>(V, lastFlag);
    }
    out_kernel<<<dim3(BB_, BH_), blk256>>>(O);
}